// round 6
// baseline (speedup 1.0000x reference)
#include <cuda_runtime.h>
#include <math.h>
#include <stdint.h>

#define BATCH 1024
#define NAG   8
#define NDUM  16
#define PLAN  128
#define HID   256
#define TP    256      /* 2*PLAN  */
#define G3    768      /* 3*HID   */
#define TB    16384    /* NDUM*BATCH */
#define AD    16       /* agents*dirs */

/* ---------------- static device scratch (alloc-free rule) ---------------- */
__device__ float g_comm[BATCH*NAG*PLAN];
__device__ int   g_empty[BATCH];
__device__ int   g_mask[TB];
__device__ int   g_seq[BATCH];
__device__ int   g_srclist[TB];
__device__ int   g_packsrc[TB];
__device__ int   g_scatrank[TB];
__device__ float g_cseq[(size_t)NAG*TB*TP];
__device__ float g_gi[(size_t)NAG*TB*1536];
__device__ float g_gh[(size_t)AD*BATCH*G3];
__device__ float g_h[(size_t)AD*BATCH*HID];
__device__ float g_out[(size_t)AD*TB*HID];
__device__ float g_scores[(size_t)NAG*TB*512];
__device__ float g_h1[(size_t)NAG*TB*HID];
__device__ float g_Wcat[(size_t)NAG*1536*TP];
__device__ float g_Whcat[(size_t)AD*G3*HID];

/* ---------------- PTX helpers ---------------- */
__device__ __forceinline__ unsigned f2t(float x) {
    unsigned u; asm("cvt.rna.tf32.f32 %0, %1;" : "=r"(u) : "f"(x)); return u;
}

#if defined(__CUDA_ARCH_FEAT_SM103_ALL) || defined(__CUDA_ARCH_FEAT_SM100_ALL)
#define HAS_TCGEN05 1
#else
#define HAS_TCGEN05 0
#endif

#if HAS_TCGEN05
__device__ __forceinline__ uint32_t smem_u32(const void* p) {
    uint32_t a;
    asm("{ .reg .u64 t; cvta.to.shared.u64 t, %1; cvt.u32.u64 %0, t; }" : "=r"(a) : "l"(p));
    return a;
}
__device__ __forceinline__ uint32_t elect_one() {
    uint32_t p;
    asm volatile("{\n\t.reg .pred p;\n\telect.sync _|p, 0xFFFFFFFF;\n\tselp.b32 %0, 1, 0, p;\n\t}" : "=r"(p));
    return p;
}
#define SW128(o) ((o) ^ (((o) >> 3) & 0x70))

#define MBAR_INIT(a, c) asm volatile("mbarrier.init.shared.b64 [%0], %1;" :: "r"(a), "r"(c) : "memory")
#define MBAR_INVAL(a)   asm volatile("mbarrier.inval.shared.b64 [%0];" :: "r"(a) : "memory")
#define MBAR_WAIT(a, ph) do {                                                       \
    asm volatile(                                                                   \
        "{\n\t.reg .pred P1;\n\t"                                                   \
        "WL_%=:\n\t"                                                                \
        "mbarrier.try_wait.parity.acquire.cta.shared::cta.b64 P1, [%0], %1, 0x989680;\n\t" \
        "@P1 bra.uni WD_%=;\n\t"                                                    \
        "bra.uni WL_%=;\n\t"                                                        \
        "WD_%=:\n\t}"                                                               \
        :: "r"(a), "r"(ph) : "memory");                                             \
} while (0)

#define T5_ALLOC(sa, n)   asm volatile("tcgen05.alloc.cta_group::1.sync.aligned.shared::cta.b32 [%0], %1;" :: "r"(sa), "r"(n) : "memory")
#define T5_DEALLOC(t, n)  asm volatile("tcgen05.dealloc.cta_group::1.sync.aligned.b32 %0, %1;" :: "r"(t), "r"(n))
#define T5_COMMIT(mb)     asm volatile("tcgen05.commit.cta_group::1.mbarrier::arrive::one.shared::cluster.b64 [%0];" :: "r"(mb) : "memory")
#define T5_FENCE_AFTER()  asm volatile("tcgen05.fence::after_thread_sync;" ::: "memory")
#define T5_FENCE_BEFORE() asm volatile("tcgen05.fence::before_thread_sync;" ::: "memory")
#define T5_WAIT_LD()      asm volatile("tcgen05.wait::ld.sync.aligned;" ::: "memory")
#define FENCE_ASYNC()     asm volatile("fence.proxy.async.shared::cta;" ::: "memory")

#define T5_LD_X32(r, a)                                                              \
    asm volatile("tcgen05.ld.sync.aligned.32x32b.x32.b32 "                           \
        "{%0,%1,%2,%3,%4,%5,%6,%7,%8,%9,%10,%11,%12,%13,%14,%15,"                    \
        "%16,%17,%18,%19,%20,%21,%22,%23,%24,%25,%26,%27,%28,%29,%30,%31}, [%32];"   \
        : "=r"((r)[0]),"=r"((r)[1]),"=r"((r)[2]),"=r"((r)[3]),                        \
          "=r"((r)[4]),"=r"((r)[5]),"=r"((r)[6]),"=r"((r)[7]),                        \
          "=r"((r)[8]),"=r"((r)[9]),"=r"((r)[10]),"=r"((r)[11]),                      \
          "=r"((r)[12]),"=r"((r)[13]),"=r"((r)[14]),"=r"((r)[15]),                    \
          "=r"((r)[16]),"=r"((r)[17]),"=r"((r)[18]),"=r"((r)[19]),                    \
          "=r"((r)[20]),"=r"((r)[21]),"=r"((r)[22]),"=r"((r)[23]),                    \
          "=r"((r)[24]),"=r"((r)[25]),"=r"((r)[26]),"=r"((r)[27]),                    \
          "=r"((r)[28]),"=r"((r)[29]),"=r"((r)[30]),"=r"((r)[31])                     \
        : "r"(a))

/* smem descriptor: SW128, version=1(Blackwell), SBO=64, LBO=1 */
#define SDESC_BASE ((2ULL<<61)|(1ULL<<46)|(64ULL<<32)|(1ULL<<16))
__device__ __forceinline__ uint64_t mkdesc(uint32_t addr) {
    return SDESC_BASE | ((uint64_t)(addr >> 4) & 0x3FFF);
}

/* idesc kind::tf32: cformat F32(1)<<4, a=b=TF32(2)<<7/<<10, N=128 -> 16<<17, M=128 -> 8<<24 */
#define IDESC_TF32 ((1u<<4)|(2u<<7)|(2u<<10)|(16u<<17)|(8u<<24))

__device__ __forceinline__ void mma_tf32_ss(uint32_t d, uint64_t da, uint64_t db, bool accum) {
    uint32_t en = accum ? 1u : 0u;
    asm volatile(
        "{\n\t.reg .pred p;\n\tsetp.ne.u32 p, %5, 0;\n\t"
        "tcgen05.mma.cta_group::1.kind::tf32 [%0], %1, %2, %3, {%4, %4, %4, %4}, p;\n\t}"
        :: "r"(d), "l"(da), "l"(db), "r"(IDESC_TF32), "r"(0u), "r"(en) : "memory");
}
#endif /* HAS_TCGEN05 */

/* ---------------- small setup kernels ---------------- */

__global__ void k_empty(const float* __restrict__ comm_plans) {
    int b = blockIdx.x;
    const float* p = comm_plans + (size_t)b*NAG*PLAN;
    int tid = threadIdx.x;
    int nz = 0;
    for (int i = tid; i < NAG*PLAN; i += 256) nz |= (p[i] != 0.0f);
    __shared__ int s[256];
    s[tid] = nz; __syncthreads();
    for (int st = 128; st > 0; st >>= 1) { if (tid < st) s[tid] |= s[tid+st]; __syncthreads(); }
    if (tid == 0) g_empty[b] = (s[0] == 0);
}

__global__ void k_comm(const float* __restrict__ plans, const float* __restrict__ comm_plans) {
    int bn = blockIdx.x;
    int b = bn >> 3, n = bn & 7;
    int p = threadIdx.x;
    float v = g_empty[b] ? plans[(size_t)bn*PLAN + p] : comm_plans[(size_t)bn*PLAN + p];
    g_comm[(size_t)bn*PLAN + p] = v;
    unsigned ball = __ballot_sync(0xffffffffu, v != 0.0f);
    __shared__ int s[4];
    if ((p & 31) == 0) s[p >> 5] = (ball != 0);
    __syncthreads();
    if (p == 0) g_mask[n*BATCH + b] = (s[0]|s[1]|s[2]|s[3]) ? 1 : 0;
}

__global__ void k_seq() {
    int b = blockIdx.x*blockDim.x + threadIdx.x;
    if (b >= BATCH) return;
    int s = 8;
    for (int n = 0; n < NAG; n++) s += g_mask[n*BATCH + b];
    g_seq[b] = s;
    for (int t = NAG; t < NDUM; t++) g_mask[t*BATCH + b] = 1;
}

/* flat row-major rank matching for pack / scatter (torch masked semantics) */
__global__ void k_scan() {
    __shared__ int wsm[16], wsp[16];
    __shared__ int sseq[BATCH];
    int tid = threadIdx.x;                 /* 512 */
    int lane = tid & 31, w = tid >> 5;
    sseq[tid] = g_seq[tid]; sseq[tid+512] = g_seq[tid+512];
    __syncthreads();
    int base = tid * 32;
    int cm = 0, cp = 0;
    int mk[32];
    #pragma unroll
    for (int q = 0; q < 8; q++) {
        int4 mv = ((const int4*)g_mask)[tid*8 + q];
        mk[q*4+0]=mv.x; mk[q*4+1]=mv.y; mk[q*4+2]=mv.z; mk[q*4+3]=mv.w;
    }
    int tb = base >> 10;
    #pragma unroll
    for (int q = 0; q < 32; q++) {
        cm += mk[q];
        cp += (tb < sseq[(base + q) & 1023]);
    }
    int im = cm, ip = cp;
    #pragma unroll
    for (int o = 1; o < 32; o <<= 1) {
        int v = __shfl_up_sync(0xffffffffu, im, o); if (lane >= o) im += v;
        v     = __shfl_up_sync(0xffffffffu, ip, o); if (lane >= o) ip += v;
    }
    if (lane == 31) { wsm[w] = im; wsp[w] = ip; }
    __syncthreads();
    if (tid == 0) {
        int am = 0, ap = 0;
        for (int i = 0; i < 16; i++) {
            int t = wsm[i]; wsm[i] = am; am += t;
            t = wsp[i];     wsp[i] = ap; ap += t;
        }
    }
    __syncthreads();
    int rm = wsm[w] + im - cm;
    #pragma unroll
    for (int q = 0; q < 32; q++) {
        int j = base + q;
        if (mk[q]) { g_srclist[rm] = j; g_scatrank[j] = rm; rm++; }
        else       { g_scatrank[j] = -1; }
    }
    __syncthreads();
    int rp = wsp[w] + ip - cp;
    #pragma unroll
    for (int q = 0; q < 32; q++) {
        int j = base + q;
        if (tb < sseq[j & 1023]) { g_packsrc[j] = g_srclist[rp]; rp++; }
        else                     { g_packsrc[j] = -1; }
    }
}

__global__ void k_wcat(const float* __restrict__ Wi_f, const float* __restrict__ Wi_b) {
    size_t idx = (size_t)blockIdx.x*256 + threadIdx.x;
    if (idx >= (size_t)NAG*1536*TP) return;
    int k = (int)(idx & 255);
    size_t r = idx >> 8;
    int g = (int)(r % 1536);
    int a = (int)(r / 1536);
    float v = (g < G3) ? Wi_f[((size_t)a*G3 + g)*TP + k]
                       : Wi_b[((size_t)a*G3 + (g - G3))*TP + k];
    g_Wcat[idx] = v;
}

__global__ void k_whcat(const float* __restrict__ Wh_f, const float* __restrict__ Wh_b) {
    size_t idx = (size_t)blockIdx.x*256 + threadIdx.x;
    if (idx >= (size_t)AD*G3*HID) return;
    int k = (int)(idx & 255);
    size_t r = idx >> 8;
    int g = (int)(r % G3);
    int z = (int)(r / G3);
    int a = z >> 1, d = z & 1;
    const float* W = d ? Wh_b : Wh_f;
    g_Whcat[idx] = W[((size_t)a*G3 + g)*HID + k];
}

__global__ void k_hinit(const float* __restrict__ hx) {
    size_t idx = (size_t)blockIdx.x*256 + threadIdx.x;
    if (idx >= (size_t)AD*BATCH*HID/4) return;
    ((float4*)g_h)[idx] = ((const float4*)hx)[idx];
}

__global__ void k_cseq(const float* __restrict__ plans, const float* __restrict__ dummy) {
    size_t idx = (size_t)blockIdx.x*256 + threadIdx.x;
    if (idx >= (size_t)NAG*TB*64) return;
    int c4 = (int)(idx & 63);
    size_t r = idx >> 6;
    int j = (int)(r % TB);
    int a = (int)(r / TB);
    float4 v = make_float4(0.f,0.f,0.f,0.f);
    int s = g_packsrc[j];
    if (s >= 0) {
        int t = s >> 10, b = s & 1023;
        if (t < NAG) {
            if (c4 < 32)
                v = ((const float4*)(plans + (size_t)(b*NAG + a)*PLAN))[c4];
            else
                v = ((const float4*)(g_comm + (size_t)(b*NAG + t)*PLAN))[c4 - 32];
        } else {
            v = ((const float4*)(dummy + ((size_t)(a*(NDUM-NAG) + (t - NAG))*BATCH + b)*TP))[c4];
        }
    }
    ((float4*)(g_cseq + ((size_t)a*TB + j)*TP))[c4] = v;
}

/* ---------------- tf32 GEMM: C[128x128] tiles, NT (C = A * Bw^T), batched by z ------
   mode 0: gi = cseq @ Wcat^T  (M=16384,N=1536,K=256, z=agent)
   mode 1: gh = h    @ Whcat^T (M=1024, N=768, K=256, z=agentdir)
   mode 2: h1 = relu(scores @ W1^T + b1) (M=16384,N=256,K=512, z=agent)
   sm_103a image: tcgen05 SS-mode. Plain sm_103 image: mma.sync.m16n8k8 fallback. */
__global__ void __launch_bounds__(256, 2) gemm_tc(int mode, const float* __restrict__ Wext,
                                                  const float* __restrict__ biasExt) {
    const float* A; const float* Bw; float* C; const float* bias = 0;
    int K, Nd, relu = 0;
    int zb = blockIdx.z;
    if (mode == 0) {
        A = g_cseq + (size_t)zb*TB*TP;   Bw = g_Wcat  + (size_t)zb*1536*TP;
        C = g_gi   + (size_t)zb*TB*1536; K = TP;  Nd = 1536;
    } else if (mode == 1) {
        A = g_h    + (size_t)zb*BATCH*HID; Bw = g_Whcat + (size_t)zb*G3*HID;
        C = g_gh   + (size_t)zb*BATCH*G3;  K = HID; Nd = G3;
    } else {
        A = g_scores + (size_t)zb*TB*512; Bw = Wext + (size_t)zb*HID*512;
        C = g_h1     + (size_t)zb*TB*HID; bias = biasExt + zb*HID;
        K = 512; Nd = HID; relu = 1;
    }
    const int m0 = blockIdx.x * 128;
    const int n0 = blockIdx.y * 128;
    const int tid = threadIdx.x;

#if HAS_TCGEN05
    /* ======== tcgen05 SS-mode path ======== */
    __shared__ __align__(1024) uint32_t sbuf[8192];   /* A: [0,4096) words ; B: [4096,8192) */
    __shared__ uint32_t s_tmem[1];
    __shared__ __align__(8) uint64_t s_mbar;

    const int wid = tid >> 5;
    const uint32_t smA = smem_u32(sbuf);
    const uint32_t smB = smA + 16384;
    const uint32_t mbar = smem_u32(&s_mbar);

    if (wid == 0) T5_ALLOC(smem_u32(s_tmem), 128);
    if (tid == 0) MBAR_INIT(mbar, 1);
    __syncthreads();
    const uint32_t tmem = s_tmem[0];

    const int row  = tid >> 1;
    const int half = tid & 1;
    const float* Arow = A  + (size_t)(m0 + row)*K + (half << 4);
    const float* Brow = Bw + (size_t)(n0 + row)*K + (half << 4);
    char* sAb = (char*)sbuf;
    char* sBb = (char*)sbuf + 16384;
    const uint32_t swb = (row << 7) + (half << 6);

    const int nk = K >> 5;
    for (int kc = 0; kc < nk; kc++) {
        #pragma unroll
        for (int i = 0; i < 4; i++) {
            float4 va = *(const float4*)(Arow + kc*32 + i*4);
            float4 vb = *(const float4*)(Brow + kc*32 + i*4);
            uint32_t off = SW128(swb + i*16);
            *(uint4*)(sAb + off) = make_uint4(f2t(va.x), f2t(va.y), f2t(va.z), f2t(va.w));
            *(uint4*)(sBb + off) = make_uint4(f2t(vb.x), f2t(vb.y), f2t(vb.z), f2t(vb.w));
        }
        __syncthreads();
        FENCE_ASYNC();
        if (wid == 0) {
            if (elect_one()) {
                uint64_t da = mkdesc(smA), db = mkdesc(smB);
                #pragma unroll
                for (int k8 = 0; k8 < 4; k8++)
                    mma_tf32_ss(tmem, da + 2*k8, db + 2*k8, (kc > 0) || (k8 > 0));
                T5_COMMIT(mbar);
            }
        }
        MBAR_WAIT(mbar, kc & 1);
        __syncthreads();
    }
    T5_FENCE_AFTER();

    if (wid < 4) {
        const int m = m0 + wid*32 + (tid & 31);
        #pragma unroll
        for (int it = 0; it < 4; it++) {
            uint32_t r[32];
            T5_LD_X32(r, tmem + it*32);
            T5_WAIT_LD();
            float v[32];
            #pragma unroll
            for (int c = 0; c < 32; c++) v[c] = __uint_as_float(r[c]);
            if (bias) {
                #pragma unroll
                for (int c = 0; c < 32; c++) v[c] += bias[n0 + it*32 + c];
            }
            if (relu) {
                #pragma unroll
                for (int c = 0; c < 32; c++) v[c] = fmaxf(v[c], 0.f);
            }
            float* crow = C + (size_t)m*Nd + n0 + it*32;
            #pragma unroll
            for (int q = 0; q < 8; q++)
                *(float4*)(crow + q*4) = make_float4(v[q*4], v[q*4+1], v[q*4+2], v[q*4+3]);
        }
        T5_FENCE_BEFORE();
    }
    __syncthreads();
    if (tid == 0) MBAR_INVAL(mbar);
    __syncthreads();
    if (wid == 0) T5_DEALLOC(tmem, 128);

#else
    /* ======== mma.sync.m16n8k8 tf32 fallback (proven round-2 path) ======== */
    __shared__ unsigned As[2][16][136];
    __shared__ unsigned Bs[2][16][136];

    const int lane = tid & 31;
    const int warp = tid >> 5;
    const int wm   = (warp & 1) << 6;
    const int wn   = (warp >> 1) << 5;
    const int lm   = tid >> 1;
    const int lk   = (tid & 1) << 3;

    const float* Ag = A  + (size_t)(m0 + lm)*K + lk;
    const float* Bg = Bw + (size_t)(n0 + lm)*K + lk;

    float acc[4][4][4];
    #pragma unroll
    for (int i = 0; i < 4; i++)
        #pragma unroll
        for (int j = 0; j < 4; j++)
            #pragma unroll
            for (int q = 0; q < 4; q++) acc[i][j][q] = 0.f;

    const int ktiles = K >> 4;
    float4 ra0 = *(const float4*)Ag;
    float4 ra1 = *(const float4*)(Ag + 4);
    float4 rb0 = *(const float4*)Bg;
    float4 rb1 = *(const float4*)(Bg + 4);

#define STORE_TILE(buf) do {                                               \
    As[buf][lk+0][lm]=f2t(ra0.x); As[buf][lk+1][lm]=f2t(ra0.y);            \
    As[buf][lk+2][lm]=f2t(ra0.z); As[buf][lk+3][lm]=f2t(ra0.w);            \
    As[buf][lk+4][lm]=f2t(ra1.x); As[buf][lk+5][lm]=f2t(ra1.y);            \
    As[buf][lk+6][lm]=f2t(ra1.z); As[buf][lk+7][lm]=f2t(ra1.w);            \
    Bs[buf][lk+0][lm]=f2t(rb0.x); Bs[buf][lk+1][lm]=f2t(rb0.y);            \
    Bs[buf][lk+2][lm]=f2t(rb0.z); Bs[buf][lk+3][lm]=f2t(rb0.w);            \
    Bs[buf][lk+4][lm]=f2t(rb1.x); Bs[buf][lk+5][lm]=f2t(rb1.y);            \
    Bs[buf][lk+6][lm]=f2t(rb1.z); Bs[buf][lk+7][lm]=f2t(rb1.w); } while(0)

    STORE_TILE(0);
    __syncthreads();

    for (int kt = 0; kt < ktiles; ++kt) {
        const int cur = kt & 1;
        if (kt + 1 < ktiles) {
            const float* Ap = Ag + ((size_t)(kt+1) << 4);
            const float* Bp = Bg + ((size_t)(kt+1) << 4);
            ra0 = *(const float4*)Ap; ra1 = *(const float4*)(Ap + 4);
            rb0 = *(const float4*)Bp; rb1 = *(const float4*)(Bp + 4);
        }
        #pragma unroll
        for (int k8 = 0; k8 < 16; k8 += 8) {
            const int kr = k8 + (lane & 3);
            const int rr = wm + (lane >> 2);
            const int nn = wn + (lane >> 2);
            unsigned af[4][4], bf[4][2];
            #pragma unroll
            for (int i = 0; i < 4; i++) {
                af[i][0] = As[cur][kr  ][rr + i*16];
                af[i][1] = As[cur][kr  ][rr + i*16 + 8];
                af[i][2] = As[cur][kr+4][rr + i*16];
                af[i][3] = As[cur][kr+4][rr + i*16 + 8];
            }
            #pragma unroll
            for (int j = 0; j < 4; j++) {
                bf[j][0] = Bs[cur][kr  ][nn + j*8];
                bf[j][1] = Bs[cur][kr+4][nn + j*8];
            }
            #pragma unroll
            for (int i = 0; i < 4; i++)
                #pragma unroll
                for (int j = 0; j < 4; j++) {
                    asm volatile(
                        "mma.sync.aligned.m16n8k8.row.col.f32.tf32.tf32.f32 "
                        "{%0,%1,%2,%3},{%4,%5,%6,%7},{%8,%9},{%0,%1,%2,%3};"
                        : "+f"(acc[i][j][0]), "+f"(acc[i][j][1]),
                          "+f"(acc[i][j][2]), "+f"(acc[i][j][3])
                        : "r"(af[i][0]), "r"(af[i][1]), "r"(af[i][2]), "r"(af[i][3]),
                          "r"(bf[j][0]), "r"(bf[j][1]));
                }
        }
        if (kt + 1 < ktiles) STORE_TILE((kt+1) & 1);
        __syncthreads();
    }

    const int cb = (lane & 3) << 1;
    #pragma unroll
    for (int i = 0; i < 4; i++) {
        #pragma unroll
        for (int j = 0; j < 4; j++) {
            int r0 = m0 + wm + i*16 + (lane >> 2);
            int c  = n0 + wn + j*8 + cb;
            float v0 = acc[i][j][0], v1 = acc[i][j][1];
            float v2 = acc[i][j][2], v3 = acc[i][j][3];
            if (bias) {
                float b0 = bias[c], b1 = bias[c+1];
                v0 += b0; v1 += b1; v2 += b0; v3 += b1;
            }
            if (relu) {
                v0 = fmaxf(v0, 0.f); v1 = fmaxf(v1, 0.f);
                v2 = fmaxf(v2, 0.f); v3 = fmaxf(v3, 0.f);
            }
            *(float2*)(C + (size_t)r0*Nd + c)       = make_float2(v0, v1);
            *(float2*)(C + (size_t)(r0+8)*Nd + c)   = make_float2(v2, v3);
        }
    }
#undef STORE_TILE
#endif
}

/* ---------------- GRU gate update (fwd+bwd), step t ---------------- */
__global__ void k_gate(int t) {
    size_t idx = (size_t)blockIdx.x*256 + threadIdx.x;
    if (idx >= (size_t)AD*BATCH*HID) return;
    int i = (int)(idx & 255);
    int b = (int)((idx >> 8) & 1023);
    int z = (int)(idx >> 18);
    int sl = g_seq[b];
    if (t >= sl) return;
    int a = z >> 1, d = z & 1;
    int ot = d ? (sl - 1 - t) : t;
    const float* gi = g_gi + ((size_t)a*TB + (size_t)ot*BATCH + b)*1536 + d*G3;
    const float* gh = g_gh + ((size_t)z*BATCH + b)*G3;
    size_t hidx = ((size_t)z*BATCH + b)*HID + i;
    float h  = g_h[hidx];
    float rr = 1.f/(1.f + expf(-(gi[i]        + gh[i])));
    float zz = 1.f/(1.f + expf(-(gi[HID+i]    + gh[HID+i])));
    float nn = tanhf(gi[2*HID+i] + rr*gh[2*HID+i]);
    float hn = (1.f - zz)*nn + zz*h;
    g_h[hidx] = hn;
    g_out[((size_t)z*TB + (size_t)ot*BATCH + b)*HID + i] = hn;
}

/* ---------------- scatter + LayerNorm ---------------- */
__global__ void k_scatln(const float* __restrict__ gamma, const float* __restrict__ beta) {
    int j = blockIdx.x, a = blockIdx.y;
    int tid = threadIdx.x;
    int c = tid * 4;
    float4 v = make_float4(0.f,0.f,0.f,0.f);
    if (g_mask[j]) {
        int r = g_scatrank[j];
        int d  = (c >= HID) ? 1 : 0;
        int cc = d ? c - HID : c;
        v = *(const float4*)(g_out + ((size_t)(a*2 + d)*TB + r)*HID + cc);
    }
    __shared__ float red[128];
    red[tid] = v.x + v.y + v.z + v.w;
    __syncthreads();
    for (int st = 64; st > 0; st >>= 1) { if (tid < st) red[tid] += red[tid+st]; __syncthreads(); }
    float mu = red[0] * (1.f/512.f);
    __syncthreads();
    float d0 = v.x-mu, d1 = v.y-mu, d2 = v.z-mu, d3 = v.w-mu;
    red[tid] = d0*d0 + d1*d1 + d2*d2 + d3*d3;
    __syncthreads();
    for (int st = 64; st > 0; st >>= 1) { if (tid < st) red[tid] += red[tid+st]; __syncthreads(); }
    float rstd = rsqrtf(red[0]*(1.f/512.f) + 1e-5f);
    float4 gg = ((const float4*)(gamma + (size_t)a*512))[tid];
    float4 bb = ((const float4*)(beta  + (size_t)a*512))[tid];
    float4 o;
    o.x = d0*rstd*gg.x + bb.x;
    o.y = d1*rstd*gg.y + bb.y;
    o.z = d2*rstd*gg.z + bb.z;
    o.w = d3*rstd*gg.w + bb.w;
    ((float4*)(g_scores + ((size_t)a*TB + j)*512))[tid] = o;
}

/* ---------------- final 2-wide projection -> coord_masks ---------------- */
__global__ void k_out2(const float* __restrict__ W2, const float* __restrict__ b2,
                       float* __restrict__ out) {
    size_t w = ((size_t)blockIdx.x*blockDim.x + threadIdx.x) >> 5;
    int lane = threadIdx.x & 31;
    if (w >= (size_t)NAG*TB) return;
    int j = (int)(w % TB);
    int a = (int)(w / TB);
    const float* h1 = g_h1 + ((size_t)a*TB + j)*HID;
    const float* w0 = W2 + (size_t)a*2*HID;
    const float* w1 = w0 + HID;
    float p0 = 0.f, p1 = 0.f;
    for (int k = lane*4; k < HID; k += 128) {
        float4 hv = *(const float4*)(h1 + k);
        float4 a0 = *(const float4*)(w0 + k);
        float4 a1 = *(const float4*)(w1 + k);
        p0 += hv.x*a0.x + hv.y*a0.y + hv.z*a0.z + hv.w*a0.w;
        p1 += hv.x*a1.x + hv.y*a1.y + hv.z*a1.z + hv.w*a1.w;
    }
    for (int s = 16; s > 0; s >>= 1) {
        p0 += __shfl_xor_sync(0xffffffffu, p0, s);
        p1 += __shfl_xor_sync(0xffffffffu, p1, s);
    }
    if (lane == 0) {
        out[w*2 + 0] = p0 + b2[a*2 + 0];
        out[w*2 + 1] = p1 + b2[a*2 + 1];
    }
}

__global__ void k_hcopy(float* __restrict__ out) {
    size_t idx = (size_t)blockIdx.x*256 + threadIdx.x;
    if (idx >= (size_t)AD*BATCH*HID/4) return;
    ((float4*)out)[idx] = ((const float4*)g_h)[idx];
}

/* ---------------- launcher ---------------- */
extern "C" void kernel_launch(void* const* d_in, const int* in_sizes, int n_in,
                              void* d_out, int out_size) {
    const float* plans      = (const float*)d_in[0];
    const float* comm_plans = (const float*)d_in[1];
    const float* hx         = (const float*)d_in[2];
    const float* dummy      = (const float*)d_in[3];
    const float* Wi_f       = (const float*)d_in[4];
    const float* Wh_f       = (const float*)d_in[5];
    const float* Wi_b       = (const float*)d_in[6];
    const float* Wh_b       = (const float*)d_in[7];
    const float* ln_g       = (const float*)d_in[8];
    const float* ln_b       = (const float*)d_in[9];
    const float* W1         = (const float*)d_in[10];
    const float* b1         = (const float*)d_in[11];
    const float* W2         = (const float*)d_in[12];
    const float* b2         = (const float*)d_in[13];
    float* out = (float*)d_out;

    k_empty<<<BATCH, 256>>>(comm_plans);
    k_comm<<<BATCH*NAG, 128>>>(plans, comm_plans);
    k_seq<<<4, 256>>>();
    k_scan<<<1, 512>>>();
    k_wcat<<<(NAG*1536*TP + 255)/256, 256>>>(Wi_f, Wi_b);
    k_whcat<<<(AD*G3*HID + 255)/256, 256>>>(Wh_f, Wh_b);
    k_hinit<<<(AD*BATCH*HID/4 + 255)/256, 256>>>(hx);
    k_cseq<<<(NAG*TB*64 + 255)/256, 256>>>(plans, dummy);

    /* input projections (both directions, all agents) */
    {
        dim3 g(TB/128, 1536/128, NAG);
        gemm_tc<<<g, 256>>>(0, (const float*)0, (const float*)0);
    }

    /* 16 recurrent steps: gh GEMM + fused gate update */
    for (int t = 0; t < NDUM; t++) {
        dim3 g(BATCH/128, G3/128, AD);
        gemm_tc<<<g, 256>>>(1, (const float*)0, (const float*)0);
        k_gate<<<(AD*BATCH*HID + 255)/256, 256>>>(t);
    }

    /* final hidden states -> d_out (coord_rnn_hxs region) */
    k_hcopy<<<(AD*BATCH*HID/4 + 255)/256, 256>>>(out + (size_t)NAG*NDUM*BATCH*2);

    /* scatter + LayerNorm */
    {
        dim3 g(TB, NAG);
        k_scatln<<<g, 128>>>(ln_g, ln_b);
    }

    /* MLP layer 1 (bias+relu fused) */
    {
        dim3 g(TB/128, HID/128, NAG);
        gemm_tc<<<g, 256>>>(2, W1, b1);
    }

    /* final projection -> coord_masks region of d_out */
    k_out2<<<(NAG*TB*32 + 255)/256, 256>>>(W2, b2, out);
}

// round 8
// speedup vs baseline: 1.0175x; 1.0175x over previous
#include <cuda_runtime.h>
#include <math.h>
#include <stdint.h>

#define BATCH 1024
#define NAG   8
#define NDUM  16
#define PLAN  128
#define HID   256
#define TP    256      /* 2*PLAN  */
#define G3    768      /* 3*HID   */
#define TB    16384    /* NDUM*BATCH */
#define AD    16       /* agents*dirs */

/* ---------------- static device scratch (alloc-free rule) ---------------- */
__device__ float g_comm[BATCH*NAG*PLAN];
__device__ int   g_empty[BATCH];
__device__ int   g_mask[TB];
__device__ int   g_seq[BATCH];
__device__ int   g_srclist[TB];
__device__ int   g_packsrc[TB];
__device__ int   g_scatrank[TB];
__device__ float g_cseq[(size_t)NAG*TB*TP];
__device__ float g_gi[(size_t)NAG*TB*1536];
__device__ float g_gh[(size_t)AD*BATCH*G3];
__device__ float g_h[(size_t)AD*BATCH*HID];
__device__ float g_out[(size_t)AD*TB*HID];
__device__ float g_scores[(size_t)NAG*TB*512];
__device__ float g_h1[(size_t)NAG*TB*HID];

/* ---------------- PTX helpers ---------------- */
__device__ __forceinline__ unsigned f2t(float x) {
    unsigned u; asm("cvt.rna.tf32.f32 %0, %1;" : "=r"(u) : "f"(x)); return u;
}

#if defined(__CUDA_ARCH_FEAT_SM103_ALL) || defined(__CUDA_ARCH_FEAT_SM100_ALL) || \
    defined(__CUDA_ARCH_SPECIFIC__) || defined(__CUDA_ARCH_FAMILY_SPECIFIC__)
#define HAS_TCGEN05 1
#else
#define HAS_TCGEN05 0
#endif

#if HAS_TCGEN05
__device__ __forceinline__ uint32_t smem_u32(const void* p) {
    uint32_t a;
    asm("{ .reg .u64 t; cvta.to.shared.u64 t, %1; cvt.u32.u64 %0, t; }" : "=r"(a) : "l"(p));
    return a;
}
__device__ __forceinline__ uint32_t elect_one() {
    uint32_t p;
    asm volatile("{\n\t.reg .pred p;\n\telect.sync _|p, 0xFFFFFFFF;\n\tselp.b32 %0, 1, 0, p;\n\t}" : "=r"(p));
    return p;
}
#define SW128(o) ((o) ^ (((o) >> 3) & 0x70))

#define MBAR_INIT(a, c) asm volatile("mbarrier.init.shared.b64 [%0], %1;" :: "r"(a), "r"(c) : "memory")
#define MBAR_INVAL(a)   asm volatile("mbarrier.inval.shared.b64 [%0];" :: "r"(a) : "memory")
#define MBAR_WAIT(a, ph) do {                                                       \
    asm volatile(                                                                   \
        "{\n\t.reg .pred P1;\n\t"                                                   \
        "WL_%=:\n\t"                                                                \
        "mbarrier.try_wait.parity.acquire.cta.shared::cta.b64 P1, [%0], %1, 0x989680;\n\t" \
        "@P1 bra.uni WD_%=;\n\t"                                                    \
        "bra.uni WL_%=;\n\t"                                                        \
        "WD_%=:\n\t}"                                                               \
        :: "r"(a), "r"(ph) : "memory");                                             \
} while (0)

#define T5_ALLOC(sa, n)   asm volatile("tcgen05.alloc.cta_group::1.sync.aligned.shared::cta.b32 [%0], %1;" :: "r"(sa), "r"(n) : "memory")
#define T5_DEALLOC(t, n)  asm volatile("tcgen05.dealloc.cta_group::1.sync.aligned.b32 %0, %1;" :: "r"(t), "r"(n))
#define T5_COMMIT(mb)     asm volatile("tcgen05.commit.cta_group::1.mbarrier::arrive::one.shared::cluster.b64 [%0];" :: "r"(mb) : "memory")
#define T5_FENCE_AFTER()  asm volatile("tcgen05.fence::after_thread_sync;" ::: "memory")
#define T5_FENCE_BEFORE() asm volatile("tcgen05.fence::before_thread_sync;" ::: "memory")
#define T5_WAIT_LD()      asm volatile("tcgen05.wait::ld.sync.aligned;" ::: "memory")
#define FENCE_ASYNC()     asm volatile("fence.proxy.async.shared::cta;" ::: "memory")

#define T5_LD_X32(r, a)                                                              \
    asm volatile("tcgen05.ld.sync.aligned.32x32b.x32.b32 "                           \
        "{%0,%1,%2,%3,%4,%5,%6,%7,%8,%9,%10,%11,%12,%13,%14,%15,"                    \
        "%16,%17,%18,%19,%20,%21,%22,%23,%24,%25,%26,%27,%28,%29,%30,%31}, [%32];"   \
        : "=r"((r)[0]),"=r"((r)[1]),"=r"((r)[2]),"=r"((r)[3]),                        \
          "=r"((r)[4]),"=r"((r)[5]),"=r"((r)[6]),"=r"((r)[7]),                        \
          "=r"((r)[8]),"=r"((r)[9]),"=r"((r)[10]),"=r"((r)[11]),                      \
          "=r"((r)[12]),"=r"((r)[13]),"=r"((r)[14]),"=r"((r)[15]),                    \
          "=r"((r)[16]),"=r"((r)[17]),"=r"((r)[18]),"=r"((r)[19]),                    \
          "=r"((r)[20]),"=r"((r)[21]),"=r"((r)[22]),"=r"((r)[23]),                    \
          "=r"((r)[24]),"=r"((r)[25]),"=r"((r)[26]),"=r"((r)[27]),                    \
          "=r"((r)[28]),"=r"((r)[29]),"=r"((r)[30]),"=r"((r)[31])                     \
        : "r"(a))

/* smem descriptor: SW128, version=1(Blackwell), SBO=64, LBO=1 */
#define SDESC_BASE ((2ULL<<61)|(1ULL<<46)|(64ULL<<32)|(1ULL<<16))
__device__ __forceinline__ uint64_t mkdesc(uint32_t addr) {
    return SDESC_BASE | ((uint64_t)(addr >> 4) & 0x3FFF);
}

/* idesc kind::tf32: cformat F32(1)<<4, a=b=TF32(2)<<7/<<10, N=128 -> 16<<17, M=128 -> 8<<24 */
#define IDESC_TF32 ((1u<<4)|(2u<<7)|(2u<<10)|(16u<<17)|(8u<<24))

__device__ __forceinline__ void mma_tf32_ss(uint32_t d, uint64_t da, uint64_t db, bool accum) {
    uint32_t en = accum ? 1u : 0u;
    asm volatile(
        "{\n\t.reg .pred p;\n\tsetp.ne.u32 p, %5, 0;\n\t"
        "tcgen05.mma.cta_group::1.kind::tf32 [%0], %1, %2, %3, {%4, %4, %4, %4}, p;\n\t}"
        :: "r"(d), "l"(da), "l"(db), "r"(IDESC_TF32), "r"(0u), "r"(en) : "memory");
}
#endif /* HAS_TCGEN05 */

/* ---------------- small setup kernels ---------------- */

__global__ void k_empty(const float* __restrict__ comm_plans) {
    int b = blockIdx.x;
    const float* p = comm_plans + (size_t)b*NAG*PLAN;
    int tid = threadIdx.x;
    int nz = 0;
    for (int i = tid; i < NAG*PLAN; i += 256) nz |= (p[i] != 0.0f);
    __shared__ int s[256];
    s[tid] = nz; __syncthreads();
    for (int st = 128; st > 0; st >>= 1) { if (tid < st) s[tid] |= s[tid+st]; __syncthreads(); }
    if (tid == 0) g_empty[b] = (s[0] == 0);
}

__global__ void k_comm(const float* __restrict__ plans, const float* __restrict__ comm_plans) {
    int bn = blockIdx.x;
    int b = bn >> 3, n = bn & 7;
    int p = threadIdx.x;
    float v = g_empty[b] ? plans[(size_t)bn*PLAN + p] : comm_plans[(size_t)bn*PLAN + p];
    g_comm[(size_t)bn*PLAN + p] = v;
    unsigned ball = __ballot_sync(0xffffffffu, v != 0.0f);
    __shared__ int s[4];
    if ((p & 31) == 0) s[p >> 5] = (ball != 0);
    __syncthreads();
    if (p == 0) g_mask[n*BATCH + b] = (s[0]|s[1]|s[2]|s[3]) ? 1 : 0;
}

__global__ void k_seq() {
    int b = blockIdx.x*blockDim.x + threadIdx.x;
    if (b >= BATCH) return;
    int s = 8;
    for (int n = 0; n < NAG; n++) s += g_mask[n*BATCH + b];
    g_seq[b] = s;
    for (int t = NAG; t < NDUM; t++) g_mask[t*BATCH + b] = 1;
}

/* flat row-major rank matching for pack / scatter (torch masked semantics) */
__global__ void k_scan() {
    __shared__ int wsm[16], wsp[16];
    __shared__ int sseq[BATCH];
    int tid = threadIdx.x;                 /* 512 */
    int lane = tid & 31, w = tid >> 5;
    sseq[tid] = g_seq[tid]; sseq[tid+512] = g_seq[tid+512];
    __syncthreads();
    int base = tid * 32;
    int cm = 0, cp = 0;
    int mk[32];
    #pragma unroll
    for (int q = 0; q < 8; q++) {
        int4 mv = ((const int4*)g_mask)[tid*8 + q];
        mk[q*4+0]=mv.x; mk[q*4+1]=mv.y; mk[q*4+2]=mv.z; mk[q*4+3]=mv.w;
    }
    int tb = base >> 10;
    #pragma unroll
    for (int q = 0; q < 32; q++) {
        cm += mk[q];
        cp += (tb < sseq[(base + q) & 1023]);
    }
    int im = cm, ip = cp;
    #pragma unroll
    for (int o = 1; o < 32; o <<= 1) {
        int v = __shfl_up_sync(0xffffffffu, im, o); if (lane >= o) im += v;
        v     = __shfl_up_sync(0xffffffffu, ip, o); if (lane >= o) ip += v;
    }
    if (lane == 31) { wsm[w] = im; wsp[w] = ip; }
    __syncthreads();
    if (tid == 0) {
        int am = 0, ap = 0;
        for (int i = 0; i < 16; i++) {
            int t = wsm[i]; wsm[i] = am; am += t;
            t = wsp[i];     wsp[i] = ap; ap += t;
        }
    }
    __syncthreads();
    int rm = wsm[w] + im - cm;
    #pragma unroll
    for (int q = 0; q < 32; q++) {
        int j = base + q;
        if (mk[q]) { g_srclist[rm] = j; g_scatrank[j] = rm; rm++; }
        else       { g_scatrank[j] = -1; }
    }
    __syncthreads();
    int rp = wsp[w] + ip - cp;
    #pragma unroll
    for (int q = 0; q < 32; q++) {
        int j = base + q;
        if (tb < sseq[j & 1023]) { g_packsrc[j] = g_srclist[rp]; rp++; }
        else                     { g_packsrc[j] = -1; }
    }
}

__global__ void k_hinit(const float* __restrict__ hx) {
    size_t idx = (size_t)blockIdx.x*256 + threadIdx.x;
    if (idx >= (size_t)AD*BATCH*HID/4) return;
    ((float4*)g_h)[idx] = ((const float4*)hx)[idx];
}

__global__ void k_cseq(const float* __restrict__ plans, const float* __restrict__ dummy) {
    size_t idx = (size_t)blockIdx.x*256 + threadIdx.x;
    if (idx >= (size_t)NAG*TB*64) return;
    int c4 = (int)(idx & 63);
    size_t r = idx >> 6;
    int j = (int)(r % TB);
    int a = (int)(r / TB);
    float4 v = make_float4(0.f,0.f,0.f,0.f);
    int s = g_packsrc[j];
    if (s >= 0) {
        int t = s >> 10, b = s & 1023;
        if (t < NAG) {
            if (c4 < 32)
                v = ((const float4*)(plans + (size_t)(b*NAG + a)*PLAN))[c4];
            else
                v = ((const float4*)(g_comm + (size_t)(b*NAG + t)*PLAN))[c4 - 32];
        } else {
            v = ((const float4*)(dummy + ((size_t)(a*(NDUM-NAG) + (t - NAG))*BATCH + b)*TP))[c4];
        }
    }
    ((float4*)(g_cseq + ((size_t)a*TB + j)*TP))[c4] = v;
}

/* ---------------- tf32 GEMM: C[128x128] tiles, NT (C = A * Bw^T), batched by z ------
   mode 0: gi = cseq @ [Wi_f;Wi_b]^T (M=16384,N=1536,K=256, z=agent)
   mode 1: gh = h @ Wh^T             (M=1024, N=768, K=256, z=agentdir)
   mode 2: h1 = relu(scores @ W1^T + b1) (M=16384,N=256,K=512, z=agent)
   sm_103a image: pipelined tcgen05 SS-mode. Plain sm_103: mma.sync fallback. */
__global__ void __launch_bounds__(256, 2) gemm_tc(int mode,
        const float* __restrict__ Wi_f, const float* __restrict__ Wi_b,
        const float* __restrict__ Wh_f, const float* __restrict__ Wh_b,
        const float* __restrict__ W1,   const float* __restrict__ b1) {
    const float* A; float* C; const float* bias = 0;
    int K, Nd, relu = 0;
    int zb = blockIdx.z;
    if (mode == 0) {
        A = g_cseq + (size_t)zb*TB*TP;
        C = g_gi   + (size_t)zb*TB*1536; K = TP;  Nd = 1536;
    } else if (mode == 1) {
        A = g_h    + (size_t)zb*BATCH*HID;
        C = g_gh   + (size_t)zb*BATCH*G3;  K = HID; Nd = G3;
    } else {
        A = g_scores + (size_t)zb*TB*512;
        C = g_h1     + (size_t)zb*TB*HID; bias = b1 + zb*HID;
        K = 512; Nd = HID; relu = 1;
    }
    const int m0 = blockIdx.x * 128;
    const int n0 = blockIdx.y * 128;
    const int tid = threadIdx.x;

#if HAS_TCGEN05
    /* ======== pipelined tcgen05 SS-mode path ======== */
    extern __shared__ __align__(1024) uint32_t dynbuf[];   /* 2 stages x 8192 words */
    __shared__ uint32_t s_tmem[1];
    __shared__ __align__(8) uint64_t s_mbar[2];

    const int wid = tid >> 5;
    const uint32_t smA0 = smem_u32(dynbuf);
    const uint32_t mb0 = smem_u32(&s_mbar[0]);
    const uint32_t mb1 = smem_u32(&s_mbar[1]);

    if (wid == 0) T5_ALLOC(smem_u32(s_tmem), 128);
    if (tid == 0) { MBAR_INIT(mb0, 1); MBAR_INIT(mb1, 1); }
    __syncthreads();
    const uint32_t tmem = s_tmem[0];

    const int row  = tid >> 1;
    const int half = tid & 1;
    const float* Arow = A + (size_t)(m0 + row)*K + (half << 4);
    const int nrow = n0 + row;
    const float* Brow;
    if (mode == 0)
        Brow = ((nrow < G3) ? Wi_f + ((size_t)zb*G3 + nrow)*TP
                            : Wi_b + ((size_t)zb*G3 + nrow - G3)*TP) + (half << 4);
    else if (mode == 1) {
        const float* W = (zb & 1) ? Wh_b : Wh_f;
        Brow = W + ((size_t)(zb >> 1)*G3 + nrow)*HID + (half << 4);
    } else
        Brow = W1 + ((size_t)zb*HID + nrow)*512 + (half << 4);

    const uint32_t swb = (row << 7) + (half << 6);
    const int nk = K >> 5;

    float4 ra[4], rb[4];
    #pragma unroll
    for (int i = 0; i < 4; i++) { ra[i] = *(const float4*)(Arow + i*4); rb[i] = *(const float4*)(Brow + i*4); }
    {   /* STS stage 0 */
        char* sA = (char*)dynbuf;
        char* sB = sA + 16384;
        #pragma unroll
        for (int i = 0; i < 4; i++) {
            uint32_t off = SW128(swb + i*16);
            *(uint4*)(sA + off) = make_uint4(f2t(ra[i].x), f2t(ra[i].y), f2t(ra[i].z), f2t(ra[i].w));
            *(uint4*)(sB + off) = make_uint4(f2t(rb[i].x), f2t(rb[i].y), f2t(rb[i].z), f2t(rb[i].w));
        }
    }
    __syncthreads();
    FENCE_ASYNC();

    for (int kc = 0; kc < nk; kc++) {
        const int st = kc & 1;
        if (wid == 0) {
            if (elect_one()) {
                uint64_t da = mkdesc(smA0 + st*32768);
                uint64_t db = mkdesc(smA0 + st*32768 + 16384);
                #pragma unroll
                for (int k8 = 0; k8 < 4; k8++)
                    mma_tf32_ss(tmem, da + 2*k8, db + 2*k8, (kc > 0) || (k8 > 0));
                T5_COMMIT(st ? mb1 : mb0);
            }
        }
        if (kc + 1 < nk) {
            const float* Ap = Arow + (size_t)(kc+1)*32;
            const float* Bp = Brow + (size_t)(kc+1)*32;
            #pragma unroll
            for (int i = 0; i < 4; i++) { ra[i] = *(const float4*)(Ap + i*4); rb[i] = *(const float4*)(Bp + i*4); }
            if (kc >= 1) {
                /* buffer (kc+1)&1 was used by MMA chunk kc-1 — wait for it */
                MBAR_WAIT(((kc-1) & 1) ? mb1 : mb0, ((kc-1) >> 1) & 1);
            }
            char* sA = (char*)dynbuf + ((kc+1) & 1)*32768;
            char* sB = sA + 16384;
            #pragma unroll
            for (int i = 0; i < 4; i++) {
                uint32_t off = SW128(swb + i*16);
                *(uint4*)(sA + off) = make_uint4(f2t(ra[i].x), f2t(ra[i].y), f2t(ra[i].z), f2t(ra[i].w));
                *(uint4*)(sB + off) = make_uint4(f2t(rb[i].x), f2t(rb[i].y), f2t(rb[i].z), f2t(rb[i].w));
            }
            __syncthreads();
            FENCE_ASYNC();
        }
    }
    /* last commit tracks completion of ALL prior MMAs */
    MBAR_WAIT(((nk-1) & 1) ? mb1 : mb0, ((nk-1) >> 1) & 1);
    T5_FENCE_AFTER();

    if (wid < 4) {
        const int m = m0 + wid*32 + (tid & 31);
        #pragma unroll
        for (int it = 0; it < 4; it++) {
            uint32_t r[32];
            T5_LD_X32(r, tmem + it*32);
            T5_WAIT_LD();
            float v[32];
            #pragma unroll
            for (int c = 0; c < 32; c++) v[c] = __uint_as_float(r[c]);
            if (bias) {
                #pragma unroll
                for (int c = 0; c < 32; c++) v[c] += bias[n0 + it*32 + c];
            }
            if (relu) {
                #pragma unroll
                for (int c = 0; c < 32; c++) v[c] = fmaxf(v[c], 0.f);
            }
            float* crow = C + (size_t)m*Nd + n0 + it*32;
            #pragma unroll
            for (int q = 0; q < 8; q++)
                *(float4*)(crow + q*4) = make_float4(v[q*4], v[q*4+1], v[q*4+2], v[q*4+3]);
        }
        T5_FENCE_BEFORE();
    }
    __syncthreads();
    if (tid == 0) { MBAR_INVAL(mb0); MBAR_INVAL(mb1); }
    __syncthreads();
    if (wid == 0) T5_DEALLOC(tmem, 128);

#else
    /* ======== mma.sync.m16n8k8 tf32 fallback ======== */
    __shared__ unsigned As[2][16][136];
    __shared__ unsigned Bs[2][16][136];

    const int lane = tid & 31;
    const int warp = tid >> 5;
    const int wm   = (warp & 1) << 6;
    const int wn   = (warp >> 1) << 5;
    const int lm   = tid >> 1;
    const int lk   = (tid & 1) << 3;

    const float* Ag = A + (size_t)(m0 + lm)*K + lk;
    const int nrow = n0 + lm;
    const float* Bg;
    if (mode == 0)
        Bg = ((nrow < G3) ? Wi_f + ((size_t)zb*G3 + nrow)*TP
                          : Wi_b + ((size_t)zb*G3 + nrow - G3)*TP) + lk;
    else if (mode == 1) {
        const float* W = (zb & 1) ? Wh_b : Wh_f;
        Bg = W + ((size_t)(zb >> 1)*G3 + nrow)*HID + lk;
    } else
        Bg = W1 + ((size_t)zb*HID + nrow)*512 + lk;

    float acc[4][4][4];
    #pragma unroll
    for (int i = 0; i < 4; i++)
        #pragma unroll
        for (int j = 0; j < 4; j++)
            #pragma unroll
            for (int q = 0; q < 4; q++) acc[i][j][q] = 0.f;

    const int ktiles = K >> 4;
    float4 ra0 = *(const float4*)Ag;
    float4 ra1 = *(const float4*)(Ag + 4);
    float4 rb0 = *(const float4*)Bg;
    float4 rb1 = *(const float4*)(Bg + 4);

#define STORE_TILE(buf) do {                                               \
    As[buf][lk+0][lm]=f2t(ra0.x); As[buf][lk+1][lm]=f2t(ra0.y);            \
    As[buf][lk+2][lm]=f2t(ra0.z); As[buf][lk+3][lm]=f2t(ra0.w);            \
    As[buf][lk+4][lm]=f2t(ra1.x); As[buf][lk+5][lm]=f2t(ra1.y);            \
    As[buf][lk+6][lm]=f2t(ra1.z); As[buf][lk+7][lm]=f2t(ra1.w);            \
    Bs[buf][lk+0][lm]=f2t(rb0.x); Bs[buf][lk+1][lm]=f2t(rb0.y);            \
    Bs[buf][lk+2][lm]=f2t(rb0.z); Bs[buf][lk+3][lm]=f2t(rb0.w);            \
    Bs[buf][lk+4][lm]=f2t(rb1.x); Bs[buf][lk+5][lm]=f2t(rb1.y);            \
    Bs[buf][lk+6][lm]=f2t(rb1.z); Bs[buf][lk+7][lm]=f2t(rb1.w); } while(0)

    STORE_TILE(0);
    __syncthreads();

    for (int kt = 0; kt < ktiles; ++kt) {
        const int cur = kt & 1;
        if (kt + 1 < ktiles) {
            const float* Ap = Ag + ((size_t)(kt+1) << 4);
            const float* Bp = Bg + ((size_t)(kt+1) << 4);
            ra0 = *(const float4*)Ap; ra1 = *(const float4*)(Ap + 4);
            rb0 = *(const float4*)Bp; rb1 = *(const float4*)(Bp + 4);
        }
        #pragma unroll
        for (int k8 = 0; k8 < 16; k8 += 8) {
            const int kr = k8 + (lane & 3);
            const int rr = wm + (lane >> 2);
            const int nn = wn + (lane >> 2);
            unsigned af[4][4], bf[4][2];
            #pragma unroll
            for (int i = 0; i < 4; i++) {
                af[i][0] = As[cur][kr  ][rr + i*16];
                af[i][1] = As[cur][kr  ][rr + i*16 + 8];
                af[i][2] = As[cur][kr+4][rr + i*16];
                af[i][3] = As[cur][kr+4][rr + i*16 + 8];
            }
            #pragma unroll
            for (int j = 0; j < 4; j++) {
                bf[j][0] = Bs[cur][kr  ][nn + j*8];
                bf[j][1] = Bs[cur][kr+4][nn + j*8];
            }
            #pragma unroll
            for (int i = 0; i < 4; i++)
                #pragma unroll
                for (int j = 0; j < 4; j++) {
                    asm volatile(
                        "mma.sync.aligned.m16n8k8.row.col.f32.tf32.tf32.f32 "
                        "{%0,%1,%2,%3},{%4,%5,%6,%7},{%8,%9},{%0,%1,%2,%3};"
                        : "+f"(acc[i][j][0]), "+f"(acc[i][j][1]),
                          "+f"(acc[i][j][2]), "+f"(acc[i][j][3])
                        : "r"(af[i][0]), "r"(af[i][1]), "r"(af[i][2]), "r"(af[i][3]),
                          "r"(bf[j][0]), "r"(bf[j][1]));
                }
        }
        if (kt + 1 < ktiles) STORE_TILE((kt+1) & 1);
        __syncthreads();
    }

    const int cb = (lane & 3) << 1;
    #pragma unroll
    for (int i = 0; i < 4; i++) {
        #pragma unroll
        for (int j = 0; j < 4; j++) {
            int r0 = m0 + wm + i*16 + (lane >> 2);
            int c  = n0 + wn + j*8 + cb;
            float v0 = acc[i][j][0], v1 = acc[i][j][1];
            float v2 = acc[i][j][2], v3 = acc[i][j][3];
            if (bias) {
                float bb0 = bias[c], bb1 = bias[c+1];
                v0 += bb0; v1 += bb1; v2 += bb0; v3 += bb1;
            }
            if (relu) {
                v0 = fmaxf(v0, 0.f); v1 = fmaxf(v1, 0.f);
                v2 = fmaxf(v2, 0.f); v3 = fmaxf(v3, 0.f);
            }
            *(float2*)(C + (size_t)r0*Nd + c)       = make_float2(v0, v1);
            *(float2*)(C + (size_t)(r0+8)*Nd + c)   = make_float2(v2, v3);
        }
    }
#undef STORE_TILE
#endif
}

/* ---------------- GRU gate update (fwd+bwd), step t ---------------- */
__global__ void k_gate(int t) {
    size_t idx = (size_t)blockIdx.x*256 + threadIdx.x;
    if (idx >= (size_t)AD*BATCH*HID) return;
    int i = (int)(idx & 255);
    int b = (int)((idx >> 8) & 1023);
    int z = (int)(idx >> 18);
    int sl = g_seq[b];
    if (t >= sl) return;
    int a = z >> 1, d = z & 1;
    int ot = d ? (sl - 1 - t) : t;
    const float* gi = g_gi + ((size_t)a*TB + (size_t)ot*BATCH + b)*1536 + d*G3;
    const float* gh = g_gh + ((size_t)z*BATCH + b)*G3;
    size_t hidx = ((size_t)z*BATCH + b)*HID + i;
    float h  = g_h[hidx];
    float rr = 1.f/(1.f + expf(-(gi[i]        + gh[i])));
    float zz = 1.f/(1.f + expf(-(gi[HID+i]    + gh[HID+i])));
    float nn = tanhf(gi[2*HID+i] + rr*gh[2*HID+i]);
    float hn = (1.f - zz)*nn + zz*h;
    g_h[hidx] = hn;
    g_out[((size_t)z*TB + (size_t)ot*BATCH + b)*HID + i] = hn;
}

/* ---------------- scatter + LayerNorm ---------------- */
__global__ void k_scatln(const float* __restrict__ gamma, const float* __restrict__ beta) {
    int j = blockIdx.x, a = blockIdx.y;
    int tid = threadIdx.x;
    int c = tid * 4;
    float4 v = make_float4(0.f,0.f,0.f,0.f);
    if (g_mask[j]) {
        int r = g_scatrank[j];
        int d  = (c >= HID) ? 1 : 0;
        int cc = d ? c - HID : c;
        v = *(const float4*)(g_out + ((size_t)(a*2 + d)*TB + r)*HID + cc);
    }
    __shared__ float red[128];
    red[tid] = v.x + v.y + v.z + v.w;
    __syncthreads();
    for (int st = 64; st > 0; st >>= 1) { if (tid < st) red[tid] += red[tid+st]; __syncthreads(); }
    float mu = red[0] * (1.f/512.f);
    __syncthreads();
    float d0 = v.x-mu, d1 = v.y-mu, d2 = v.z-mu, d3 = v.w-mu;
    red[tid] = d0*d0 + d1*d1 + d2*d2 + d3*d3;
    __syncthreads();
    for (int st = 64; st > 0; st >>= 1) { if (tid < st) red[tid] += red[tid+st]; __syncthreads(); }
    float rstd = rsqrtf(red[0]*(1.f/512.f) + 1e-5f);
    float4 gg = ((const float4*)(gamma + (size_t)a*512))[tid];
    float4 bb = ((const float4*)(beta  + (size_t)a*512))[tid];
    float4 o;
    o.x = d0*rstd*gg.x + bb.x;
    o.y = d1*rstd*gg.y + bb.y;
    o.z = d2*rstd*gg.z + bb.z;
    o.w = d3*rstd*gg.w + bb.w;
    ((float4*)(g_scores + ((size_t)a*TB + j)*512))[tid] = o;
}

/* ---------------- final 2-wide projection -> coord_masks ---------------- */
__global__ void k_out2(const float* __restrict__ W2, const float* __restrict__ b2,
                       float* __restrict__ out) {
    size_t w = ((size_t)blockIdx.x*blockDim.x + threadIdx.x) >> 5;
    int lane = threadIdx.x & 31;
    if (w >= (size_t)NAG*TB) return;
    int j = (int)(w % TB);
    int a = (int)(w / TB);
    const float* h1 = g_h1 + ((size_t)a*TB + j)*HID;
    const float* w0 = W2 + (size_t)a*2*HID;
    const float* w1 = w0 + HID;
    float p0 = 0.f, p1 = 0.f;
    for (int k = lane*4; k < HID; k += 128) {
        float4 hv = *(const float4*)(h1 + k);
        float4 a0 = *(const float4*)(w0 + k);
        float4 a1 = *(const float4*)(w1 + k);
        p0 += hv.x*a0.x + hv.y*a0.y + hv.z*a0.z + hv.w*a0.w;
        p1 += hv.x*a1.x + hv.y*a1.y + hv.z*a1.z + hv.w*a1.w;
    }
    for (int s = 16; s > 0; s >>= 1) {
        p0 += __shfl_xor_sync(0xffffffffu, p0, s);
        p1 += __shfl_xor_sync(0xffffffffu, p1, s);
    }
    if (lane == 0) {
        out[w*2 + 0] = p0 + b2[a*2 + 0];
        out[w*2 + 1] = p1 + b2[a*2 + 1];
    }
}

__global__ void k_hcopy(float* __restrict__ out) {
    size_t idx = (size_t)blockIdx.x*256 + threadIdx.x;
    if (idx >= (size_t)AD*BATCH*HID/4) return;
    ((float4*)out)[idx] = ((const float4*)g_h)[idx];
}

/* ---------------- launcher ---------------- */
#define GEMM_DSMEM 65536

extern "C" void kernel_launch(void* const* d_in, const int* in_sizes, int n_in,
                              void* d_out, int out_size) {
    const float* plans      = (const float*)d_in[0];
    const float* comm_plans = (const float*)d_in[1];
    const float* hx         = (const float*)d_in[2];
    const float* dummy      = (const float*)d_in[3];
    const float* Wi_f       = (const float*)d_in[4];
    const float* Wh_f       = (const float*)d_in[5];
    const float* Wi_b       = (const float*)d_in[6];
    const float* Wh_b       = (const float*)d_in[7];
    const float* ln_g       = (const float*)d_in[8];
    const float* ln_b       = (const float*)d_in[9];
    const float* W1         = (const float*)d_in[10];
    const float* b1         = (const float*)d_in[11];
    const float* W2         = (const float*)d_in[12];
    const float* b2         = (const float*)d_in[13];
    float* out = (float*)d_out;

    cudaFuncSetAttribute(gemm_tc, cudaFuncAttributeMaxDynamicSharedMemorySize, GEMM_DSMEM);

    /* launches 1-5 */
    k_empty<<<BATCH, 256>>>(comm_plans);
    k_comm<<<BATCH*NAG, 128>>>(plans, comm_plans);
    k_seq<<<4, 256>>>();
    k_scan<<<1, 512>>>();
    k_cseq<<<(NAG*TB*64 + 255)/256, 256>>>(plans, dummy);

    /* launch 6 — profiled by ncu (-s 5 -c 1): the big input-projection GEMM */
    {
        dim3 g(TB/128, 1536/128, NAG);
        gemm_tc<<<g, 256, GEMM_DSMEM>>>(0, Wi_f, Wi_b, Wh_f, Wh_b, W1, b1);
    }

    k_hinit<<<(AD*BATCH*HID/4 + 255)/256, 256>>>(hx);

    /* 16 recurrent steps: gh GEMM + fused gate update */
    for (int t = 0; t < NDUM; t++) {
        dim3 g(BATCH/128, G3/128, AD);
        gemm_tc<<<g, 256, GEMM_DSMEM>>>(1, Wi_f, Wi_b, Wh_f, Wh_b, W1, b1);
        k_gate<<<(AD*BATCH*HID + 255)/256, 256>>>(t);
    }

    /* final hidden states -> d_out (coord_rnn_hxs region) */
    k_hcopy<<<(AD*BATCH*HID/4 + 255)/256, 256>>>(out + (size_t)NAG*NDUM*BATCH*2);

    /* scatter + LayerNorm */
    {
        dim3 g(TB, NAG);
        k_scatln<<<g, 128>>>(ln_g, ln_b);
    }

    /* MLP layer 1 (bias+relu fused) */
    {
        dim3 g(TB/128, HID/128, NAG);
        gemm_tc<<<g, 256, GEMM_DSMEM>>>(2, Wi_f, Wi_b, Wh_f, Wh_b, W1, b1);
    }

    /* final projection -> coord_masks region of d_out */
    k_out2<<<(NAG*TB*32 + 255)/256, 256>>>(W2, b2, out);
}

// round 9
// speedup vs baseline: 1.5455x; 1.5189x over previous
#include <cuda_runtime.h>
#include <cuda_fp16.h>
#include <math.h>
#include <stdint.h>

#define BATCH 1024
#define NAG   8
#define NDUM  16
#define PLAN  128
#define HID   256
#define TP    256      /* 2*PLAN  */
#define G3    768      /* 3*HID   */
#define TB    16384    /* NDUM*BATCH */
#define AD    16       /* agents*dirs */

/* ---------------- static device scratch (alloc-free rule) ---------------- */
__device__ float  g_comm[BATCH*NAG*PLAN];
__device__ int    g_empty[BATCH];
__device__ int    g_mask[TB];
__device__ int    g_seq[BATCH];
__device__ int    g_packsrc[TB];
__device__ int    g_scatrank[TB];
__device__ __half g_cseq[(size_t)NAG*TB*TP];
__device__ __half g_gi[(size_t)NAG*TB*1536];
__device__ __half g_gh[(size_t)AD*BATCH*G3];
__device__ float  g_h[(size_t)AD*BATCH*HID];
__device__ float  g_out[(size_t)AD*TB*HID];
__device__ float  g_scores[(size_t)NAG*TB*512];
__device__ float  g_h1[(size_t)NAG*TB*HID];

__device__ __forceinline__ uint32_t f2h2(float lo, float hi) {
    __half2 h = __floats2half2_rn(lo, hi);
    return *(uint32_t*)&h;
}

/* ---------------- small setup kernels ---------------- */

__global__ void k_empty(const float* __restrict__ comm_plans) {
    int b = blockIdx.x;
    const float* p = comm_plans + (size_t)b*NAG*PLAN;
    int tid = threadIdx.x;
    int nz = 0;
    for (int i = tid; i < NAG*PLAN; i += 256) nz |= (p[i] != 0.0f);
    __shared__ int s[256];
    s[tid] = nz; __syncthreads();
    for (int st = 128; st > 0; st >>= 1) { if (tid < st) s[tid] |= s[tid+st]; __syncthreads(); }
    if (tid == 0) g_empty[b] = (s[0] == 0);
}

__global__ void k_comm(const float* __restrict__ plans, const float* __restrict__ comm_plans) {
    int bn = blockIdx.x;
    int b = bn >> 3, n = bn & 7;
    int p = threadIdx.x;
    float v = g_empty[b] ? plans[(size_t)bn*PLAN + p] : comm_plans[(size_t)bn*PLAN + p];
    g_comm[(size_t)bn*PLAN + p] = v;
    unsigned ball = __ballot_sync(0xffffffffu, v != 0.0f);
    __shared__ int s[4];
    if ((p & 31) == 0) s[p >> 5] = (ball != 0);
    __syncthreads();
    if (p == 0) g_mask[n*BATCH + b] = (s[0]|s[1]|s[2]|s[3]) ? 1 : 0;
}

__global__ void k_seq() {
    int b = blockIdx.x*blockDim.x + threadIdx.x;
    if (b >= BATCH) return;
    int s = 8;
    for (int n = 0; n < NAG; n++) s += g_mask[n*BATCH + b];
    g_seq[b] = s;
    for (int t = NAG; t < NDUM; t++) g_mask[t*BATCH + b] = 1;
}

/* flat row-major rank matching for pack / scatter (torch masked semantics) */
__global__ void k_scan() {
    extern __shared__ int s_srclist[];        /* TB ints = 64KB dynamic */
    __shared__ int wsm[16], wsp[16];
    __shared__ int sseq[BATCH];
    int tid = threadIdx.x;                    /* 512 */
    int lane = tid & 31, w = tid >> 5;
    sseq[tid] = g_seq[tid]; sseq[tid+512] = g_seq[tid+512];
    __syncthreads();
    int base = tid * 32;
    int cm = 0, cp = 0;
    int mk[32];
    #pragma unroll
    for (int q = 0; q < 8; q++) {
        int4 mv = ((const int4*)g_mask)[tid*8 + q];
        mk[q*4+0]=mv.x; mk[q*4+1]=mv.y; mk[q*4+2]=mv.z; mk[q*4+3]=mv.w;
    }
    int tb = base >> 10;
    #pragma unroll
    for (int q = 0; q < 32; q++) {
        cm += mk[q];
        cp += (tb < sseq[(base + q) & 1023]);
    }
    int im = cm, ip = cp;
    #pragma unroll
    for (int o = 1; o < 32; o <<= 1) {
        int v = __shfl_up_sync(0xffffffffu, im, o); if (lane >= o) im += v;
        v     = __shfl_up_sync(0xffffffffu, ip, o); if (lane >= o) ip += v;
    }
    if (lane == 31) { wsm[w] = im; wsp[w] = ip; }
    __syncthreads();
    if (tid == 0) {
        int am = 0, ap = 0;
        for (int i = 0; i < 16; i++) {
            int t = wsm[i]; wsm[i] = am; am += t;
            t = wsp[i];     wsp[i] = ap; ap += t;
        }
    }
    __syncthreads();
    int rm = wsm[w] + im - cm;
    #pragma unroll
    for (int q = 0; q < 32; q++) {
        int j = base + q;
        if (mk[q]) { s_srclist[rm] = j; g_scatrank[j] = rm; rm++; }
        else       { g_scatrank[j] = -1; }
    }
    __syncthreads();
    int rp = wsp[w] + ip - cp;
    #pragma unroll
    for (int q = 0; q < 32; q++) {
        int j = base + q;
        if (tb < sseq[j & 1023]) { g_packsrc[j] = s_srclist[rp]; rp++; }
        else                     { g_packsrc[j] = -1; }
    }
}

__global__ void k_hinit(const float* __restrict__ hx) {
    size_t idx = (size_t)blockIdx.x*256 + threadIdx.x;
    if (idx >= (size_t)AD*BATCH*HID/4) return;
    ((float4*)g_h)[idx] = ((const float4*)hx)[idx];
}

/* build packed sequence input per agent (gathers via pack_src), fp16 output */
__global__ void k_cseq(const float* __restrict__ plans, const float* __restrict__ dummy) {
    size_t idx = (size_t)blockIdx.x*256 + threadIdx.x;
    if (idx >= (size_t)NAG*TB*64) return;
    int c4 = (int)(idx & 63);
    size_t r = idx >> 6;
    int j = (int)(r % TB);
    int a = (int)(r / TB);
    float4 v = make_float4(0.f,0.f,0.f,0.f);
    int s = g_packsrc[j];
    if (s >= 0) {
        int t = s >> 10, b = s & 1023;
        if (t < NAG) {
            if (c4 < 32)
                v = ((const float4*)(plans + (size_t)(b*NAG + a)*PLAN))[c4];
            else
                v = ((const float4*)(g_comm + (size_t)(b*NAG + t)*PLAN))[c4 - 32];
        } else {
            v = ((const float4*)(dummy + ((size_t)(a*(NDUM-NAG) + (t - NAG))*BATCH + b)*TP))[c4];
        }
    }
    uint2 u;
    u.x = f2h2(v.x, v.y);
    u.y = f2h2(v.z, v.w);
    *(uint2*)(g_cseq + ((size_t)a*TB + j)*TP + c4*4) = u;
}

/* ---------------- fp16 tensor-core GEMM (NT: C = A * Bw^T), batched by z ----------
   mode 0: gi = cseq @ [Wi_f;Wi_b]^T (M=16384,N=1536,K=256, z=agent)  C: fp16
   mode 1: gh = h @ Wh^T             (M=1024, N=768, K=256, z=agentdir) C: fp16
   mode 2: h1 = relu(scores @ W1^T + b1) (M=16384,N=256,K=512, z=agent) C: fp32
   BM=BN=128, BK=32, double-buffered, 8 warps (2x4), warp 64x32, mma.m16n8k16.f16 */
__global__ void __launch_bounds__(256, 2) gemm_fp16(int mode,
        const float* __restrict__ Wi_f, const float* __restrict__ Wi_b,
        const float* __restrict__ Wh_f, const float* __restrict__ Wh_b,
        const float* __restrict__ W1,   const float* __restrict__ b1) {
    const __half* Ah = 0; const float* Af = 0;
    __half* Ch = 0; float* Cf = 0; const float* bias = 0;
    int K, Nd, relu = 0;
    const int zb = blockIdx.z;
    if (mode == 0) {
        Ah = g_cseq + (size_t)zb*TB*TP;  Ch = g_gi + (size_t)zb*TB*1536;
        K = TP; Nd = 1536;
    } else if (mode == 1) {
        Af = g_h + (size_t)zb*BATCH*HID; Ch = g_gh + (size_t)zb*BATCH*G3;
        K = HID; Nd = G3;
    } else {
        Af = g_scores + (size_t)zb*TB*512; Cf = g_h1 + (size_t)zb*TB*HID;
        bias = b1 + zb*HID; K = 512; Nd = HID; relu = 1;
    }
    const int m0 = blockIdx.y * 128;
    const int n0 = blockIdx.x * 128;
    const int tid = threadIdx.x, lane = tid & 31, warp = tid >> 5;
    const int wm = (warp & 1) << 6, wn = (warp >> 1) << 5;

    /* [buf][k16chunk][k2][m] half2-packed words; 136 stride => bank = 8*k2 + m mod 32 */
    __shared__ uint32_t As[2][2][8][136];
    __shared__ uint32_t Bs[2][2][8][136];

    const int row = tid >> 1;            /* 0..127 */
    const int kh  = (tid & 1) << 4;      /* 0 or 16 (k offset) */
    const int ch  = tid & 1;             /* k16 chunk this thread fills */

    const __half* ArH = (mode == 0) ? Ah + (size_t)(m0 + row)*K + kh : (const __half*)0;
    const float*  ArF = (mode != 0) ? Af + (size_t)(m0 + row)*K + kh : (const float*)0;
    const int nrow = n0 + row;
    const float* Br;
    if (mode == 0)
        Br = ((nrow < G3) ? Wi_f + ((size_t)zb*G3 + nrow)*TP
                          : Wi_b + ((size_t)zb*G3 + nrow - G3)*TP) + kh;
    else if (mode == 1) {
        const float* W = (zb & 1) ? Wh_b : Wh_f;
        Br = W + ((size_t)(zb >> 1)*G3 + nrow)*HID + kh;
    } else
        Br = W1 + ((size_t)zb*HID + nrow)*512 + kh;

    float acc[4][4][4];
    #pragma unroll
    for (int i = 0; i < 4; i++)
        #pragma unroll
        for (int j = 0; j < 4; j++)
            #pragma unroll
            for (int q = 0; q < 4; q++) acc[i][j][q] = 0.f;

    uint32_t aw[8], bw[8];

#define LOAD_STAGE(kt) do {                                                       \
    if (mode == 0) {                                                              \
        const uint4* p = (const uint4*)(ArH + (kt)*32);                           \
        uint4 q0 = p[0], q1 = p[1];                                               \
        aw[0]=q0.x; aw[1]=q0.y; aw[2]=q0.z; aw[3]=q0.w;                           \
        aw[4]=q1.x; aw[5]=q1.y; aw[6]=q1.z; aw[7]=q1.w;                           \
    } else {                                                                      \
        const float4* p = (const float4*)(ArF + (kt)*32);                         \
        _Pragma("unroll")                                                         \
        for (int i = 0; i < 4; i++) {                                             \
            float4 v = p[i];                                                      \
            aw[2*i] = f2h2(v.x, v.y); aw[2*i+1] = f2h2(v.z, v.w);                 \
        }                                                                         \
    }                                                                             \
    {                                                                             \
        const float4* q = (const float4*)(Br + (kt)*32);                          \
        _Pragma("unroll")                                                         \
        for (int i = 0; i < 4; i++) {                                             \
            float4 v = q[i];                                                      \
            bw[2*i] = f2h2(v.x, v.y); bw[2*i+1] = f2h2(v.z, v.w);                 \
        }                                                                         \
    }                                                                             \
} while (0)

#define STS_STAGE(buf) do {                                                       \
    _Pragma("unroll")                                                             \
    for (int w = 0; w < 8; w++) {                                                 \
        As[buf][ch][w][row] = aw[w];                                              \
        Bs[buf][ch][w][row] = bw[w];                                              \
    }                                                                             \
} while (0)

    const int nk = K >> 5;
    LOAD_STAGE(0);
    STS_STAGE(0);
    __syncthreads();

    for (int kt = 0; kt < nk; kt++) {
        if (kt + 1 < nk) LOAD_STAGE(kt + 1);
        const int buf = kt & 1;
        const int kr = lane & 3, rg = lane >> 2;
        #pragma unroll
        for (int cc = 0; cc < 2; cc++) {
            uint32_t bf[4][2];
            #pragma unroll
            for (int j = 0; j < 4; j++) {
                bf[j][0] = Bs[buf][cc][kr  ][wn + 8*j + rg];
                bf[j][1] = Bs[buf][cc][kr+4][wn + 8*j + rg];
            }
            #pragma unroll
            for (int i = 0; i < 4; i++) {
                uint32_t a0 = As[buf][cc][kr  ][wm + 16*i + rg];
                uint32_t a1 = As[buf][cc][kr  ][wm + 16*i + rg + 8];
                uint32_t a2 = As[buf][cc][kr+4][wm + 16*i + rg];
                uint32_t a3 = As[buf][cc][kr+4][wm + 16*i + rg + 8];
                #pragma unroll
                for (int j = 0; j < 4; j++) {
                    asm volatile(
                        "mma.sync.aligned.m16n8k16.row.col.f32.f16.f16.f32 "
                        "{%0,%1,%2,%3},{%4,%5,%6,%7},{%8,%9},{%0,%1,%2,%3};"
                        : "+f"(acc[i][j][0]), "+f"(acc[i][j][1]),
                          "+f"(acc[i][j][2]), "+f"(acc[i][j][3])
                        : "r"(a0), "r"(a1), "r"(a2), "r"(a3),
                          "r"(bf[j][0]), "r"(bf[j][1]));
                }
            }
        }
        if (kt + 1 < nk) STS_STAGE((kt + 1) & 1);
        __syncthreads();
    }
#undef LOAD_STAGE
#undef STS_STAGE

    const int cb = (lane & 3) << 1;
    #pragma unroll
    for (int i = 0; i < 4; i++) {
        #pragma unroll
        for (int j = 0; j < 4; j++) {
            int r0 = m0 + wm + 16*i + (lane >> 2);
            int c  = n0 + wn + 8*j + cb;
            float v0 = acc[i][j][0], v1 = acc[i][j][1];
            float v2 = acc[i][j][2], v3 = acc[i][j][3];
            if (mode < 2) {
                *(__half2*)(Ch + (size_t)r0*Nd + c)     = __floats2half2_rn(v0, v1);
                *(__half2*)(Ch + (size_t)(r0+8)*Nd + c) = __floats2half2_rn(v2, v3);
            } else {
                float bb0 = bias[c], bb1 = bias[c+1];
                v0 += bb0; v1 += bb1; v2 += bb0; v3 += bb1;
                if (relu) {
                    v0 = fmaxf(v0, 0.f); v1 = fmaxf(v1, 0.f);
                    v2 = fmaxf(v2, 0.f); v3 = fmaxf(v3, 0.f);
                }
                *(float2*)(Cf + (size_t)r0*Nd + c)     = make_float2(v0, v1);
                *(float2*)(Cf + (size_t)(r0+8)*Nd + c) = make_float2(v2, v3);
            }
        }
    }
}

/* ---------------- GRU gate update (fwd+bwd), step t ---------------- */
__global__ void k_gate(int t) {
    size_t idx = (size_t)blockIdx.x*256 + threadIdx.x;
    if (idx >= (size_t)AD*BATCH*HID) return;
    int i = (int)(idx & 255);
    int b = (int)((idx >> 8) & 1023);
    int z = (int)(idx >> 18);
    int sl = g_seq[b];
    if (t >= sl) return;
    int a = z >> 1, d = z & 1;
    int ot = d ? (sl - 1 - t) : t;
    const __half* gi = g_gi + ((size_t)a*TB + (size_t)ot*BATCH + b)*1536 + d*G3;
    const __half* gh = g_gh + ((size_t)z*BATCH + b)*G3;
    size_t hidx = ((size_t)z*BATCH + b)*HID + i;
    float h  = g_h[hidx];
    float gr = __half2float(gi[i])       + __half2float(gh[i]);
    float gz = __half2float(gi[HID+i])   + __half2float(gh[HID+i]);
    float gn = __half2float(gi[2*HID+i]);
    float hn_g = __half2float(gh[2*HID+i]);
    float rr = 1.f/(1.f + expf(-gr));
    float zz = 1.f/(1.f + expf(-gz));
    float nn = tanhf(gn + rr*hn_g);
    float hn = (1.f - zz)*nn + zz*h;
    g_h[hidx] = hn;
    g_out[((size_t)z*TB + (size_t)ot*BATCH + b)*HID + i] = hn;
}

/* ---------------- scatter + LayerNorm ---------------- */
__global__ void k_scatln(const float* __restrict__ gamma, const float* __restrict__ beta) {
    int j = blockIdx.x, a = blockIdx.y;
    int tid = threadIdx.x;
    int c = tid * 4;
    float4 v = make_float4(0.f,0.f,0.f,0.f);
    if (g_mask[j]) {
        int r = g_scatrank[j];
        int d  = (c >= HID) ? 1 : 0;
        int cc = d ? c - HID : c;
        v = *(const float4*)(g_out + ((size_t)(a*2 + d)*TB + r)*HID + cc);
    }
    __shared__ float red[128];
    red[tid] = v.x + v.y + v.z + v.w;
    __syncthreads();
    for (int st = 64; st > 0; st >>= 1) { if (tid < st) red[tid] += red[tid+st]; __syncthreads(); }
    float mu = red[0] * (1.f/512.f);
    __syncthreads();
    float d0 = v.x-mu, d1 = v.y-mu, d2 = v.z-mu, d3 = v.w-mu;
    red[tid] = d0*d0 + d1*d1 + d2*d2 + d3*d3;
    __syncthreads();
    for (int st = 64; st > 0; st >>= 1) { if (tid < st) red[tid] += red[tid+st]; __syncthreads(); }
    float rstd = rsqrtf(red[0]*(1.f/512.f) + 1e-5f);
    float4 gg = ((const float4*)(gamma + (size_t)a*512))[tid];
    float4 bb = ((const float4*)(beta  + (size_t)a*512))[tid];
    float4 o;
    o.x = d0*rstd*gg.x + bb.x;
    o.y = d1*rstd*gg.y + bb.y;
    o.z = d2*rstd*gg.z + bb.z;
    o.w = d3*rstd*gg.w + bb.w;
    ((float4*)(g_scores + ((size_t)a*TB + j)*512))[tid] = o;
}

/* ---------------- final 2-wide projection -> coord_masks ---------------- */
__global__ void k_out2(const float* __restrict__ W2, const float* __restrict__ b2,
                       float* __restrict__ out) {
    size_t w = ((size_t)blockIdx.x*blockDim.x + threadIdx.x) >> 5;
    int lane = threadIdx.x & 31;
    if (w >= (size_t)NAG*TB) return;
    int j = (int)(w % TB);
    int a = (int)(w / TB);
    const float* h1 = g_h1 + ((size_t)a*TB + j)*HID;
    const float* w0 = W2 + (size_t)a*2*HID;
    const float* w1 = w0 + HID;
    float p0 = 0.f, p1 = 0.f;
    for (int k = lane*4; k < HID; k += 128) {
        float4 hv = *(const float4*)(h1 + k);
        float4 a0 = *(const float4*)(w0 + k);
        float4 a1 = *(const float4*)(w1 + k);
        p0 += hv.x*a0.x + hv.y*a0.y + hv.z*a0.z + hv.w*a0.w;
        p1 += hv.x*a1.x + hv.y*a1.y + hv.z*a1.z + hv.w*a1.w;
    }
    for (int s = 16; s > 0; s >>= 1) {
        p0 += __shfl_xor_sync(0xffffffffu, p0, s);
        p1 += __shfl_xor_sync(0xffffffffu, p1, s);
    }
    if (lane == 0) {
        out[w*2 + 0] = p0 + b2[a*2 + 0];
        out[w*2 + 1] = p1 + b2[a*2 + 1];
    }
}

__global__ void k_hcopy(float* __restrict__ out) {
    size_t idx = (size_t)blockIdx.x*256 + threadIdx.x;
    if (idx >= (size_t)AD*BATCH*HID/4) return;
    ((float4*)out)[idx] = ((const float4*)g_h)[idx];
}

/* ---------------- launcher ---------------- */
extern "C" void kernel_launch(void* const* d_in, const int* in_sizes, int n_in,
                              void* d_out, int out_size) {
    const float* plans      = (const float*)d_in[0];
    const float* comm_plans = (const float*)d_in[1];
    const float* hx         = (const float*)d_in[2];
    const float* dummy      = (const float*)d_in[3];
    const float* Wi_f       = (const float*)d_in[4];
    const float* Wh_f       = (const float*)d_in[5];
    const float* Wi_b       = (const float*)d_in[6];
    const float* Wh_b       = (const float*)d_in[7];
    const float* ln_g       = (const float*)d_in[8];
    const float* ln_b       = (const float*)d_in[9];
    const float* W1         = (const float*)d_in[10];
    const float* b1         = (const float*)d_in[11];
    const float* W2         = (const float*)d_in[12];
    const float* b2         = (const float*)d_in[13];
    float* out = (float*)d_out;

    static int attr_done = 0;
    if (!attr_done) {
        cudaFuncSetAttribute(k_scan, cudaFuncAttributeMaxDynamicSharedMemorySize, TB*4);
        attr_done = 1;
    }

    k_empty<<<BATCH, 256>>>(comm_plans);
    k_comm<<<BATCH*NAG, 128>>>(plans, comm_plans);
    k_seq<<<4, 256>>>();
    k_scan<<<1, 512, TB*4>>>();
    k_cseq<<<(NAG*TB*64 + 255)/256, 256>>>(plans, dummy);

    /* input projections (both directions, all agents): x = n-tiles for A reuse in L2 */
    {
        dim3 g(1536/128, TB/128, NAG);
        gemm_fp16<<<g, 256>>>(0, Wi_f, Wi_b, Wh_f, Wh_b, W1, b1);
    }

    k_hinit<<<(AD*BATCH*HID/4 + 255)/256, 256>>>(hx);

    /* 16 recurrent steps: gh GEMM + fused gate update */
    for (int t = 0; t < NDUM; t++) {
        dim3 g(G3/128, BATCH/128, AD);
        gemm_fp16<<<g, 256>>>(1, Wi_f, Wi_b, Wh_f, Wh_b, W1, b1);
        k_gate<<<(AD*BATCH*HID + 255)/256, 256>>>(t);
    }

    /* final hidden states -> d_out (coord_rnn_hxs region) */
    k_hcopy<<<(AD*BATCH*HID/4 + 255)/256, 256>>>(out + (size_t)NAG*NDUM*BATCH*2);

    /* scatter + LayerNorm */
    {
        dim3 g(TB, NAG);
        k_scatln<<<g, 128>>>(ln_g, ln_b);
    }

    /* MLP layer 1 (bias+relu fused) */
    {
        dim3 g(HID/128, TB/128, NAG);
        gemm_fp16<<<g, 256>>>(2, Wi_f, Wi_b, Wh_f, Wh_b, W1, b1);
    }

    /* final projection -> coord_masks region of d_out */
    k_out2<<<(NAG*TB*32 + 255)/256, 256>>>(W2, b2, out);
}

// round 10
// speedup vs baseline: 1.7209x; 1.1134x over previous
#include <cuda_runtime.h>
#include <cuda_fp16.h>
#include <math.h>
#include <stdint.h>

#define BATCH 1024
#define NAG   8
#define NDUM  16
#define PLAN  128
#define HID   256
#define TP    256      /* 2*PLAN  */
#define G3    768      /* 3*HID   */
#define TB    16384    /* NDUM*BATCH */
#define AD    16       /* agents*dirs */

/* ---------------- static device scratch (alloc-free rule) ---------------- */
__device__ float  g_comm[BATCH*NAG*PLAN];
__device__ int    g_empty[BATCH];
__device__ int    g_mask[TB];
__device__ int    g_seq[BATCH];
__device__ int    g_packsrc[TB];
__device__ int    g_scatrank[TB];
__device__ __half g_cseq[(size_t)NAG*TB*TP];
__device__ __half g_gi[(size_t)NAG*TB*1536];
__device__ __half g_gh[(size_t)AD*BATCH*G3];
__device__ float  g_h[(size_t)AD*BATCH*HID];
__device__ __half g_h16[(size_t)AD*BATCH*HID];
__device__ float  g_out[(size_t)AD*TB*HID];
__device__ __half g_sc16[(size_t)NAG*TB*512];
__device__ float  g_h1[(size_t)NAG*TB*HID];
__device__ __half g_wi16[(size_t)NAG*1536*TP];
__device__ __half g_wh16[(size_t)AD*G3*HID];
__device__ __half g_w116[(size_t)NAG*HID*512];

__device__ __forceinline__ uint32_t f2h2(float lo, float hi) {
    __half2 h = __floats2half2_rn(lo, hi);
    return *(uint32_t*)&h;
}

/* ---------------- small setup kernels ---------------- */

__global__ void k_empty(const float* __restrict__ comm_plans) {
    int b = blockIdx.x;
    const float* p = comm_plans + (size_t)b*NAG*PLAN;
    int tid = threadIdx.x;
    int nz = 0;
    for (int i = tid; i < NAG*PLAN; i += 256) nz |= (p[i] != 0.0f);
    __shared__ int s[256];
    s[tid] = nz; __syncthreads();
    for (int st = 128; st > 0; st >>= 1) { if (tid < st) s[tid] |= s[tid+st]; __syncthreads(); }
    if (tid == 0) g_empty[b] = (s[0] == 0);
}

__global__ void k_comm(const float* __restrict__ plans, const float* __restrict__ comm_plans) {
    int bn = blockIdx.x;
    int b = bn >> 3, n = bn & 7;
    int p = threadIdx.x;
    float v = g_empty[b] ? plans[(size_t)bn*PLAN + p] : comm_plans[(size_t)bn*PLAN + p];
    g_comm[(size_t)bn*PLAN + p] = v;
    unsigned ball = __ballot_sync(0xffffffffu, v != 0.0f);
    __shared__ int s[4];
    if ((p & 31) == 0) s[p >> 5] = (ball != 0);
    __syncthreads();
    if (p == 0) g_mask[n*BATCH + b] = (s[0]|s[1]|s[2]|s[3]) ? 1 : 0;
}

__global__ void k_seq() {
    int b = blockIdx.x*blockDim.x + threadIdx.x;
    if (b >= BATCH) return;
    int s = 8;
    for (int n = 0; n < NAG; n++) s += g_mask[n*BATCH + b];
    g_seq[b] = s;
    for (int t = NAG; t < NDUM; t++) g_mask[t*BATCH + b] = 1;
}

/* flat row-major rank matching for pack / scatter (torch masked semantics) */
__global__ void k_scan() {
    extern __shared__ int s_srclist[];        /* TB ints */
    __shared__ int wsm[16], wsp[16];
    __shared__ int sseq[BATCH];
    int tid = threadIdx.x;                    /* 512 */
    int lane = tid & 31, w = tid >> 5;
    sseq[tid] = g_seq[tid]; sseq[tid+512] = g_seq[tid+512];
    __syncthreads();
    int base = tid * 32;
    int cm = 0, cp = 0;
    int mk[32];
    #pragma unroll
    for (int q = 0; q < 8; q++) {
        int4 mv = ((const int4*)g_mask)[tid*8 + q];
        mk[q*4+0]=mv.x; mk[q*4+1]=mv.y; mk[q*4+2]=mv.z; mk[q*4+3]=mv.w;
    }
    int tb = base >> 10;
    #pragma unroll
    for (int q = 0; q < 32; q++) {
        cm += mk[q];
        cp += (tb < sseq[(base + q) & 1023]);
    }
    int im = cm, ip = cp;
    #pragma unroll
    for (int o = 1; o < 32; o <<= 1) {
        int v = __shfl_up_sync(0xffffffffu, im, o); if (lane >= o) im += v;
        v     = __shfl_up_sync(0xffffffffu, ip, o); if (lane >= o) ip += v;
    }
    if (lane == 31) { wsm[w] = im; wsp[w] = ip; }
    __syncthreads();
    if (tid == 0) {
        int am = 0, ap = 0;
        for (int i = 0; i < 16; i++) {
            int t = wsm[i]; wsm[i] = am; am += t;
            t = wsp[i];     wsp[i] = ap; ap += t;
        }
    }
    __syncthreads();
    int rm = wsm[w] + im - cm;
    #pragma unroll
    for (int q = 0; q < 32; q++) {
        int j = base + q;
        if (mk[q]) { s_srclist[rm] = j; g_scatrank[j] = rm; rm++; }
        else       { g_scatrank[j] = -1; }
    }
    __syncthreads();
    int rp = wsp[w] + ip - cp;
    #pragma unroll
    for (int q = 0; q < 32; q++) {
        int j = base + q;
        if (tb < sseq[j & 1023]) { g_packsrc[j] = s_srclist[rp]; rp++; }
        else                     { g_packsrc[j] = -1; }
    }
}

/* one-time fp32 -> fp16 weight conversion (runs every replay, ~8us) */
__global__ void k_wconv(const float* __restrict__ Wi_f, const float* __restrict__ Wi_b,
                        const float* __restrict__ Wh_f, const float* __restrict__ Wh_b,
                        const float* __restrict__ W1) {
    const size_t n_wi = (size_t)NAG*1536*TP/8;
    const size_t n_wh = (size_t)AD*G3*HID/8;
    const size_t n_w1 = (size_t)NAG*HID*512/8;
    size_t i8 = (size_t)blockIdx.x*256 + threadIdx.x;
    const float* src; __half* dst;
    if (i8 < n_wi) {
        size_t e = i8*8;
        int k = (int)(e & 255); size_t r = e >> 8;
        int g = (int)(r % 1536); int a = (int)(r / 1536);
        src = (g < G3) ? Wi_f + ((size_t)a*G3 + g)*TP + k
                       : Wi_b + ((size_t)a*G3 + g - G3)*TP + k;
        dst = g_wi16 + e;
    } else if (i8 < n_wi + n_wh) {
        size_t e = (i8 - n_wi)*8;
        int k = (int)(e & 255); size_t r = e >> 8;
        int g = (int)(r % G3); int z = (int)(r / G3);
        const float* W = (z & 1) ? Wh_b : Wh_f;
        src = W + ((size_t)(z >> 1)*G3 + g)*HID + k;
        dst = g_wh16 + e;
    } else if (i8 < n_wi + n_wh + n_w1) {
        size_t e = (i8 - n_wi - n_wh)*8;
        src = W1 + e;                /* same contiguous layout */
        dst = g_w116 + e;
    } else return;
    float4 v0 = ((const float4*)src)[0], v1 = ((const float4*)src)[1];
    uint4 o;
    o.x = f2h2(v0.x, v0.y); o.y = f2h2(v0.z, v0.w);
    o.z = f2h2(v1.x, v1.y); o.w = f2h2(v1.z, v1.w);
    *(uint4*)dst = o;
}

__global__ void k_hinit(const float* __restrict__ hx) {
    size_t idx = (size_t)blockIdx.x*256 + threadIdx.x;
    if (idx >= (size_t)AD*BATCH*HID/4) return;
    float4 v = ((const float4*)hx)[idx];
    ((float4*)g_h)[idx] = v;
    uint2 u; u.x = f2h2(v.x, v.y); u.y = f2h2(v.z, v.w);
    ((uint2*)g_h16)[idx] = u;
}

/* build packed sequence input per agent (gathers via pack_src), fp16 output */
__global__ void k_cseq(const float* __restrict__ plans, const float* __restrict__ dummy) {
    size_t idx = (size_t)blockIdx.x*256 + threadIdx.x;
    if (idx >= (size_t)NAG*TB*64) return;
    int c4 = (int)(idx & 63);
    size_t r = idx >> 6;
    int j = (int)(r % TB);
    int a = (int)(r / TB);
    float4 v = make_float4(0.f,0.f,0.f,0.f);
    int s = g_packsrc[j];
    if (s >= 0) {
        int t = s >> 10, b = s & 1023;
        if (t < NAG) {
            if (c4 < 32)
                v = ((const float4*)(plans + (size_t)(b*NAG + a)*PLAN))[c4];
            else
                v = ((const float4*)(g_comm + (size_t)(b*NAG + t)*PLAN))[c4 - 32];
        } else {
            v = ((const float4*)(dummy + ((size_t)(a*(NDUM-NAG) + (t - NAG))*BATCH + b)*TP))[c4];
        }
    }
    uint2 u;
    u.x = f2h2(v.x, v.y);
    u.y = f2h2(v.z, v.w);
    *(uint2*)(g_cseq + ((size_t)a*TB + j)*TP + c4*4) = u;
}

/* ---------------- fp16 tensor-core GEMM, all operands fp16 (NT), batched by z -----
   mode 0: gi = cseq @ wi16^T  (M=16384,N=1536,K=256, z=agent)   C fp16
   mode 1: gh = h16 @ wh16^T   (M=1024, N=768, K=256, z=agentdir) C fp16
   mode 2: h1 = relu(sc16 @ w116^T + b1) (M=16384,N=256,K=512, z=agent) C fp32
   BM=128, BN=256, BK=32, 256 thr (8 warps, 2m x 4n), warp 64x64, double-buffered. */

/* dynamic smem word indices; A cc-stride 1104 (bank +16 per cc => conflict-free STS) */
#define SA(s,cc,k2,r) dsm[(s)*2208 + (cc)*1104 + (k2)*136 + (r)]
#define SB(s,cc,k2,n) dsm[4416 + (s)*4224 + (cc)*2112 + (k2)*264 + (n)]
#define GEMM_SMEM ((4416 + 8448) * 4)

__global__ void __launch_bounds__(256) gemm_fp16(int mode, const float* __restrict__ b1) {
    extern __shared__ uint32_t dsm[];
    const __half* A; const __half* B;
    __half* Ch = 0; float* Cf = 0; const float* bias = 0;
    int K, Nd, relu = 0;
    const int zb = blockIdx.z;
    if (mode == 0) {
        A = g_cseq + (size_t)zb*TB*TP;    B = g_wi16 + (size_t)zb*1536*TP;
        Ch = g_gi + (size_t)zb*TB*1536;   K = 256; Nd = 1536;
    } else if (mode == 1) {
        A = g_h16 + (size_t)zb*BATCH*HID; B = g_wh16 + (size_t)zb*G3*HID;
        Ch = g_gh + (size_t)zb*BATCH*G3;  K = 256; Nd = G3;
    } else {
        A = g_sc16 + (size_t)zb*TB*512;   B = g_w116 + (size_t)zb*HID*512;
        Cf = g_h1 + (size_t)zb*TB*HID;    bias = b1 + zb*HID;
        K = 512; Nd = HID; relu = 1;
    }
    const int m0 = blockIdx.y * 128;
    const int n0 = blockIdx.x * 256;
    const int tid = threadIdx.x, lane = tid & 31, warp = tid >> 5;
    const int wm = (warp & 1) << 6, wn = (warp >> 1) << 6;

    const int ra = tid >> 1, ccA = tid & 1;
    const int rb = tid;
    const __half* gA = A + (size_t)(m0 + ra)*K + (ccA << 4);
    const __half* gB = B + (size_t)(n0 + rb)*K;

    float acc[4][8][4];
    #pragma unroll
    for (int i = 0; i < 4; i++)
        #pragma unroll
        for (int j = 0; j < 8; j++)
            #pragma unroll
            for (int q = 0; q < 4; q++) acc[i][j][q] = 0.f;

    uint4 pa0, pa1, pb0, pb1, pb2, pb3;

#define LOADG(kt) do {                                                   \
    const uint4* p = (const uint4*)(gA + (size_t)(kt)*32);               \
    pa0 = p[0]; pa1 = p[1];                                              \
    const uint4* q = (const uint4*)(gB + (size_t)(kt)*32);               \
    pb0 = q[0]; pb1 = q[1]; pb2 = q[2]; pb3 = q[3];                      \
} while (0)

#define STSG(s) do {                                                     \
    SA(s,ccA,0,ra)=pa0.x; SA(s,ccA,1,ra)=pa0.y;                          \
    SA(s,ccA,2,ra)=pa0.z; SA(s,ccA,3,ra)=pa0.w;                          \
    SA(s,ccA,4,ra)=pa1.x; SA(s,ccA,5,ra)=pa1.y;                          \
    SA(s,ccA,6,ra)=pa1.z; SA(s,ccA,7,ra)=pa1.w;                          \
    SB(s,0,0,rb)=pb0.x; SB(s,0,1,rb)=pb0.y; SB(s,0,2,rb)=pb0.z; SB(s,0,3,rb)=pb0.w; \
    SB(s,0,4,rb)=pb1.x; SB(s,0,5,rb)=pb1.y; SB(s,0,6,rb)=pb1.z; SB(s,0,7,rb)=pb1.w; \
    SB(s,1,0,rb)=pb2.x; SB(s,1,1,rb)=pb2.y; SB(s,1,2,rb)=pb2.z; SB(s,1,3,rb)=pb2.w; \
    SB(s,1,4,rb)=pb3.x; SB(s,1,5,rb)=pb3.y; SB(s,1,6,rb)=pb3.z; SB(s,1,7,rb)=pb3.w; \
} while (0)

    const int nk = K >> 5;
    LOADG(0);
    STSG(0);
    __syncthreads();

    const int kr = lane & 3, rg = lane >> 2;
    for (int kt = 0; kt < nk; kt++) {
        if (kt + 1 < nk) LOADG(kt + 1);
        const int buf = kt & 1;
        #pragma unroll
        for (int cc = 0; cc < 2; cc++) {
            uint32_t bf[8][2];
            #pragma unroll
            for (int j = 0; j < 8; j++) {
                bf[j][0] = SB(buf, cc, kr,   wn + 8*j + rg);
                bf[j][1] = SB(buf, cc, kr+4, wn + 8*j + rg);
            }
            #pragma unroll
            for (int i = 0; i < 4; i++) {
                uint32_t a0 = SA(buf, cc, kr,   wm + 16*i + rg);
                uint32_t a1 = SA(buf, cc, kr,   wm + 16*i + rg + 8);
                uint32_t a2 = SA(buf, cc, kr+4, wm + 16*i + rg);
                uint32_t a3 = SA(buf, cc, kr+4, wm + 16*i + rg + 8);
                #pragma unroll
                for (int j = 0; j < 8; j++) {
                    asm volatile(
                        "mma.sync.aligned.m16n8k16.row.col.f32.f16.f16.f32 "
                        "{%0,%1,%2,%3},{%4,%5,%6,%7},{%8,%9},{%0,%1,%2,%3};"
                        : "+f"(acc[i][j][0]), "+f"(acc[i][j][1]),
                          "+f"(acc[i][j][2]), "+f"(acc[i][j][3])
                        : "r"(a0), "r"(a1), "r"(a2), "r"(a3),
                          "r"(bf[j][0]), "r"(bf[j][1]));
                }
            }
        }
        if (kt + 1 < nk) STSG((kt + 1) & 1);
        __syncthreads();
    }
#undef LOADG
#undef STSG

    const int cb = (lane & 3) << 1;
    #pragma unroll
    for (int i = 0; i < 4; i++) {
        #pragma unroll
        for (int j = 0; j < 8; j++) {
            int r0 = m0 + wm + 16*i + rg;
            int c  = n0 + wn + 8*j + cb;
            float v0 = acc[i][j][0], v1 = acc[i][j][1];
            float v2 = acc[i][j][2], v3 = acc[i][j][3];
            if (mode < 2) {
                *(__half2*)(Ch + (size_t)r0*Nd + c)     = __floats2half2_rn(v0, v1);
                *(__half2*)(Ch + (size_t)(r0+8)*Nd + c) = __floats2half2_rn(v2, v3);
            } else {
                float bb0 = bias[c], bb1 = bias[c+1];
                v0 += bb0; v1 += bb1; v2 += bb0; v3 += bb1;
                if (relu) {
                    v0 = fmaxf(v0, 0.f); v1 = fmaxf(v1, 0.f);
                    v2 = fmaxf(v2, 0.f); v3 = fmaxf(v3, 0.f);
                }
                *(float2*)(Cf + (size_t)r0*Nd + c)     = make_float2(v0, v1);
                *(float2*)(Cf + (size_t)(r0+8)*Nd + c) = make_float2(v2, v3);
            }
        }
    }
}

/* ---------------- GRU gate update (fwd+bwd), step t ---------------- */
__global__ void k_gate(int t) {
    size_t idx = (size_t)blockIdx.x*256 + threadIdx.x;
    if (idx >= (size_t)AD*BATCH*HID) return;
    int i = (int)(idx & 255);
    int b = (int)((idx >> 8) & 1023);
    int z = (int)(idx >> 18);
    int sl = g_seq[b];
    if (t >= sl) return;
    int a = z >> 1, d = z & 1;
    int ot = d ? (sl - 1 - t) : t;
    const __half* gi = g_gi + ((size_t)a*TB + (size_t)ot*BATCH + b)*1536 + d*G3;
    const __half* gh = g_gh + ((size_t)z*BATCH + b)*G3;
    size_t hidx = ((size_t)z*BATCH + b)*HID + i;
    float h  = g_h[hidx];
    float gr = __half2float(gi[i])       + __half2float(gh[i]);
    float gz = __half2float(gi[HID+i])   + __half2float(gh[HID+i]);
    float gn = __half2float(gi[2*HID+i]);
    float hn_g = __half2float(gh[2*HID+i]);
    float rr = 1.f/(1.f + expf(-gr));
    float zz = 1.f/(1.f + expf(-gz));
    float nn = tanhf(gn + rr*hn_g);
    float hn = (1.f - zz)*nn + zz*h;
    g_h[hidx] = hn;
    g_h16[hidx] = __float2half(hn);
    g_out[((size_t)z*TB + (size_t)ot*BATCH + b)*HID + i] = hn;
}

/* ---------------- scatter + LayerNorm (fp16 output for MLP GEMM) ---------------- */
__global__ void k_scatln(const float* __restrict__ gamma, const float* __restrict__ beta) {
    int j = blockIdx.x, a = blockIdx.y;
    int tid = threadIdx.x;
    int c = tid * 4;
    float4 v = make_float4(0.f,0.f,0.f,0.f);
    if (g_mask[j]) {
        int r = g_scatrank[j];
        int d  = (c >= HID) ? 1 : 0;
        int cc = d ? c - HID : c;
        v = *(const float4*)(g_out + ((size_t)(a*2 + d)*TB + r)*HID + cc);
    }
    __shared__ float red[128];
    red[tid] = v.x + v.y + v.z + v.w;
    __syncthreads();
    for (int st = 64; st > 0; st >>= 1) { if (tid < st) red[tid] += red[tid+st]; __syncthreads(); }
    float mu = red[0] * (1.f/512.f);
    __syncthreads();
    float d0 = v.x-mu, d1 = v.y-mu, d2 = v.z-mu, d3 = v.w-mu;
    red[tid] = d0*d0 + d1*d1 + d2*d2 + d3*d3;
    __syncthreads();
    for (int st = 64; st > 0; st >>= 1) { if (tid < st) red[tid] += red[tid+st]; __syncthreads(); }
    float rstd = rsqrtf(red[0]*(1.f/512.f) + 1e-5f);
    float4 gg = ((const float4*)(gamma + (size_t)a*512))[tid];
    float4 bb = ((const float4*)(beta  + (size_t)a*512))[tid];
    float o0 = d0*rstd*gg.x + bb.x;
    float o1 = d1*rstd*gg.y + bb.y;
    float o2 = d2*rstd*gg.z + bb.z;
    float o3 = d3*rstd*gg.w + bb.w;
    uint2 u; u.x = f2h2(o0, o1); u.y = f2h2(o2, o3);
    *(uint2*)(g_sc16 + ((size_t)a*TB + j)*512 + c) = u;
}

/* ---------------- final 2-wide projection -> coord_masks ---------------- */
__global__ void k_out2(const float* __restrict__ W2, const float* __restrict__ b2,
                       float* __restrict__ out) {
    size_t w = ((size_t)blockIdx.x*blockDim.x + threadIdx.x) >> 5;
    int lane = threadIdx.x & 31;
    if (w >= (size_t)NAG*TB) return;
    int j = (int)(w % TB);
    int a = (int)(w / TB);
    const float* h1 = g_h1 + ((size_t)a*TB + j)*HID;
    const float* w0 = W2 + (size_t)a*2*HID;
    const float* w1 = w0 + HID;
    float p0 = 0.f, p1 = 0.f;
    for (int k = lane*4; k < HID; k += 128) {
        float4 hv = *(const float4*)(h1 + k);
        float4 a0 = *(const float4*)(w0 + k);
        float4 a1 = *(const float4*)(w1 + k);
        p0 += hv.x*a0.x + hv.y*a0.y + hv.z*a0.z + hv.w*a0.w;
        p1 += hv.x*a1.x + hv.y*a1.y + hv.z*a1.z + hv.w*a1.w;
    }
    for (int s = 16; s > 0; s >>= 1) {
        p0 += __shfl_xor_sync(0xffffffffu, p0, s);
        p1 += __shfl_xor_sync(0xffffffffu, p1, s);
    }
    if (lane == 0) {
        out[w*2 + 0] = p0 + b2[a*2 + 0];
        out[w*2 + 1] = p1 + b2[a*2 + 1];
    }
}

__global__ void k_hcopy(float* __restrict__ out) {
    size_t idx = (size_t)blockIdx.x*256 + threadIdx.x;
    if (idx >= (size_t)AD*BATCH*HID/4) return;
    ((float4*)out)[idx] = ((const float4*)g_h)[idx];
}

/* ---------------- launcher ---------------- */
extern "C" void kernel_launch(void* const* d_in, const int* in_sizes, int n_in,
                              void* d_out, int out_size) {
    const float* plans      = (const float*)d_in[0];
    const float* comm_plans = (const float*)d_in[1];
    const float* hx         = (const float*)d_in[2];
    const float* dummy      = (const float*)d_in[3];
    const float* Wi_f       = (const float*)d_in[4];
    const float* Wh_f       = (const float*)d_in[5];
    const float* Wi_b       = (const float*)d_in[6];
    const float* Wh_b       = (const float*)d_in[7];
    const float* ln_g       = (const float*)d_in[8];
    const float* ln_b       = (const float*)d_in[9];
    const float* W1         = (const float*)d_in[10];
    const float* b1         = (const float*)d_in[11];
    const float* W2         = (const float*)d_in[12];
    const float* b2         = (const float*)d_in[13];
    float* out = (float*)d_out;

    static int attr_done = 0;
    if (!attr_done) {
        cudaFuncSetAttribute(k_scan, cudaFuncAttributeMaxDynamicSharedMemorySize, TB*4);
        cudaFuncSetAttribute(gemm_fp16, cudaFuncAttributeMaxDynamicSharedMemorySize, GEMM_SMEM);
        attr_done = 1;
    }

    k_empty<<<BATCH, 256>>>(comm_plans);
    k_comm<<<BATCH*NAG, 128>>>(plans, comm_plans);
    k_seq<<<4, 256>>>();
    k_scan<<<1, 512, TB*4>>>();
    k_wconv<<<3584, 256>>>(Wi_f, Wi_b, Wh_f, Wh_b, W1);
    k_cseq<<<(NAG*TB*64 + 255)/256, 256>>>(plans, dummy);
    k_hinit<<<(AD*BATCH*HID/4 + 255)/256, 256>>>(hx);

    /* input projections (both directions, all agents) */
    {
        dim3 g(1536/256, TB/128, NAG);
        gemm_fp16<<<g, 256, GEMM_SMEM>>>(0, b1);
    }

    /* 16 recurrent steps: gh GEMM + fused gate update */
    for (int t = 0; t < NDUM; t++) {
        dim3 g(G3/256, BATCH/128, AD);
        gemm_fp16<<<g, 256, GEMM_SMEM>>>(1, b1);
        k_gate<<<(AD*BATCH*HID + 255)/256, 256>>>(t);
    }

    /* final hidden states -> d_out (coord_rnn_hxs region) */
    k_hcopy<<<(AD*BATCH*HID/4 + 255)/256, 256>>>(out + (size_t)NAG*NDUM*BATCH*2);

    /* scatter + LayerNorm -> fp16 scores */
    {
        dim3 g(TB, NAG);
        k_scatln<<<g, 128>>>(ln_g, ln_b);
    }

    /* MLP layer 1 (bias+relu fused) */
    {
        dim3 g(1, TB/128, NAG);
        gemm_fp16<<<g, 256, GEMM_SMEM>>>(2, b1);
    }

    /* final projection -> coord_masks region of d_out */
    k_out2<<<(NAG*TB*32 + 255)/256, 256>>>(W2, b2, out);
}

// round 13
// speedup vs baseline: 2.0605x; 1.1974x over previous
#include <cuda_runtime.h>
#include <cuda_fp16.h>
#include <math.h>
#include <stdint.h>

#define BATCH 1024
#define NAG   8
#define NDUM  16
#define PLAN  128
#define HID   256
#define TP    256      /* 2*PLAN  */
#define G3    768      /* 3*HID   */
#define TB    16384    /* NDUM*BATCH */
#define AD    16       /* agents*dirs */

/* ---------------- static device scratch (alloc-free rule) ---------------- */
__device__ float  g_comm[BATCH*NAG*PLAN];
__device__ int    g_mask[NAG*BATCH];
__device__ int    g_seq[BATCH];
__device__ int    g_packsrc[TB];
__device__ int    g_scatrank[TB];
__device__ __half g_cseq[(size_t)NAG*TB*TP];
__device__ __half g_gi[(size_t)NAG*TB*1536];
__device__ __half g_gh[(size_t)AD*BATCH*G3];
__device__ float  g_h[(size_t)AD*BATCH*HID];
__device__ __half g_h16[(size_t)AD*BATCH*HID];
__device__ __half g_out16[(size_t)AD*TB*HID];
__device__ __half g_sc16[(size_t)NAG*TB*512];
__device__ __half g_wi16[(size_t)NAG*1536*TP];
__device__ __half g_wh16[(size_t)AD*G3*HID];
__device__ __half g_w116[(size_t)NAG*HID*512];

__device__ __forceinline__ uint32_t f2h2(float lo, float hi) {
    __half2 h = __floats2half2_rn(lo, hi);
    return *(uint32_t*)&h;
}

/* ---------------- setup: empty-check + comm select + mask + seq ---------------- */
__global__ void k_prep(const float* __restrict__ plans, const float* __restrict__ comm_plans) {
    int b = blockIdx.x;
    int tid = threadIdx.x, lane = tid & 31, w = tid >> 5;
    __shared__ int sred[8], smask[8], sempty;
    float4 cv = ((const float4*)(comm_plans + (size_t)b*1024))[tid];
    int nz = (cv.x!=0.f)||(cv.y!=0.f)||(cv.z!=0.f)||(cv.w!=0.f);
    unsigned ball = __ballot_sync(0xffffffffu, nz);
    if (lane == 0) sred[w] = (ball != 0);
    __syncthreads();
    if (tid == 0) {
        int e = 0;
        #pragma unroll
        for (int q = 0; q < 8; q++) e |= sred[q];
        sempty = !e;
    }
    __syncthreads();
    float4 pv = sempty ? ((const float4*)(plans + (size_t)b*1024))[tid] : cv;
    ((float4*)(g_comm + (size_t)b*1024))[tid] = pv;
    int nzz = (pv.x!=0.f)||(pv.y!=0.f)||(pv.z!=0.f)||(pv.w!=0.f);
    unsigned bm = __ballot_sync(0xffffffffu, nzz);
    if (lane == 0) { int m = (bm != 0); g_mask[w*BATCH + b] = m; smask[w] = m; }
    __syncthreads();
    if (tid == 0) {
        int s = 8;
        #pragma unroll
        for (int q = 0; q < 8; q++) s += smask[q];
        g_seq[b] = s;
    }
}

/* flat row-major rank matching for pack / scatter (torch masked semantics).
   t >= 8 rows have mask==1 implicitly. */
__global__ void k_scan() {
    extern __shared__ int s_srclist[];        /* TB ints */
    __shared__ int wsm[16], wsp[16];
    __shared__ int sseq[BATCH];
    int tid = threadIdx.x;                    /* 512 */
    int lane = tid & 31, w = tid >> 5;
    sseq[tid] = g_seq[tid]; sseq[tid+512] = g_seq[tid+512];
    __syncthreads();
    int base = tid * 32;
    int cm = 0, cp = 0;
    int mk[32];
    if (tid < 256) {
        #pragma unroll
        for (int q = 0; q < 8; q++) {
            int4 mv = ((const int4*)g_mask)[tid*8 + q];
            mk[q*4+0]=mv.x; mk[q*4+1]=mv.y; mk[q*4+2]=mv.z; mk[q*4+3]=mv.w;
        }
    } else {
        #pragma unroll
        for (int q = 0; q < 32; q++) mk[q] = 1;
    }
    int tb = base >> 10;
    #pragma unroll
    for (int q = 0; q < 32; q++) {
        cm += mk[q];
        cp += (tb < sseq[(base + q) & 1023]);
    }
    int im = cm, ip = cp;
    #pragma unroll
    for (int o = 1; o < 32; o <<= 1) {
        int v = __shfl_up_sync(0xffffffffu, im, o); if (lane >= o) im += v;
        v     = __shfl_up_sync(0xffffffffu, ip, o); if (lane >= o) ip += v;
    }
    if (lane == 31) { wsm[w] = im; wsp[w] = ip; }
    __syncthreads();
    if (tid == 0) {
        int am = 0, ap = 0;
        for (int i = 0; i < 16; i++) {
            int t = wsm[i]; wsm[i] = am; am += t;
            t = wsp[i];     wsp[i] = ap; ap += t;
        }
    }
    __syncthreads();
    int rm = wsm[w] + im - cm;
    #pragma unroll
    for (int q = 0; q < 32; q++) {
        int j = base + q;
        if (mk[q]) { s_srclist[rm] = j; g_scatrank[j] = rm; rm++; }
        else       { g_scatrank[j] = -1; }
    }
    __syncthreads();
    int rp = wsp[w] + ip - cp;
    #pragma unroll
    for (int q = 0; q < 32; q++) {
        int j = base + q;
        if (tb < sseq[j & 1023]) { g_packsrc[j] = s_srclist[rp]; rp++; }
        else                     { g_packsrc[j] = -1; }
    }
}

/* fp32 -> fp16 weight conversion */
__global__ void k_wconv(const float* __restrict__ Wi_f, const float* __restrict__ Wi_b,
                        const float* __restrict__ Wh_f, const float* __restrict__ Wh_b,
                        const float* __restrict__ W1) {
    const size_t n_wi = (size_t)NAG*1536*TP/8;
    const size_t n_wh = (size_t)AD*G3*HID/8;
    const size_t n_w1 = (size_t)NAG*HID*512/8;
    size_t i8 = (size_t)blockIdx.x*256 + threadIdx.x;
    const float* src; __half* dst;
    if (i8 < n_wi) {
        size_t e = i8*8;
        int k = (int)(e & 255); size_t r = e >> 8;
        int g = (int)(r % 1536); int a = (int)(r / 1536);
        src = (g < G3) ? Wi_f + ((size_t)a*G3 + g)*TP + k
                       : Wi_b + ((size_t)a*G3 + g - G3)*TP + k;
        dst = g_wi16 + e;
    } else if (i8 < n_wi + n_wh) {
        size_t e = (i8 - n_wi)*8;
        int k = (int)(e & 255); size_t r = e >> 8;
        int g = (int)(r % G3); int z = (int)(r / G3);
        const float* W = (z & 1) ? Wh_b : Wh_f;
        src = W + ((size_t)(z >> 1)*G3 + g)*HID + k;
        dst = g_wh16 + e;
    } else if (i8 < n_wi + n_wh + n_w1) {
        size_t e = (i8 - n_wi - n_wh)*8;
        src = W1 + e;
        dst = g_w116 + e;
    } else return;
    float4 v0 = ((const float4*)src)[0], v1 = ((const float4*)src)[1];
    uint4 o;
    o.x = f2h2(v0.x, v0.y); o.y = f2h2(v0.z, v0.w);
    o.z = f2h2(v1.x, v1.y); o.w = f2h2(v1.z, v1.w);
    *(uint4*)dst = o;
}

__global__ void k_hinit(const float* __restrict__ hx) {
    size_t idx = (size_t)blockIdx.x*256 + threadIdx.x;
    if (idx >= (size_t)AD*BATCH*HID/4) return;
    float4 v = ((const float4*)hx)[idx];
    ((float4*)g_h)[idx] = v;
    uint2 u; u.x = f2h2(v.x, v.y); u.y = f2h2(v.z, v.w);
    ((uint2*)g_h16)[idx] = u;
}

/* build packed sequence input per agent (gathers via pack_src), fp16 output */
__global__ void k_cseq(const float* __restrict__ plans, const float* __restrict__ dummy) {
    size_t idx = (size_t)blockIdx.x*256 + threadIdx.x;
    if (idx >= (size_t)NAG*TB*64) return;
    int c4 = (int)(idx & 63);
    size_t r = idx >> 6;
    int j = (int)(r % TB);
    int a = (int)(r / TB);
    float4 v = make_float4(0.f,0.f,0.f,0.f);
    int s = g_packsrc[j];
    if (s >= 0) {
        int t = s >> 10, b = s & 1023;
        if (t < NAG) {
            if (c4 < 32)
                v = ((const float4*)(plans + (size_t)(b*NAG + a)*PLAN))[c4];
            else
                v = ((const float4*)(g_comm + (size_t)(b*NAG + t)*PLAN))[c4 - 32];
        } else {
            v = ((const float4*)(dummy + ((size_t)(a*(NDUM-NAG) + (t - NAG))*BATCH + b)*TP))[c4];
        }
    }
    uint2 u;
    u.x = f2h2(v.x, v.y);
    u.y = f2h2(v.z, v.w);
    *(uint2*)(g_cseq + ((size_t)a*TB + j)*TP + c4*4) = u;
}

/* ---------------- fp16 GEMM, cp.async 3-stage pipeline (NT), batched by z --------
   mode 0: gi = cseq @ wi16^T  (M=16384,N=1536,K=256, z=agent)   -> fp16
   mode 1: gh = h16 @ wh16^T   (M=1024, N=768, K=256, z=agentdir) -> fp16
   mode 2: cm = (relu(sc16 @ w116^T + b1)) @ W2^T + b2  fused epilogue -> fp32 out
   BM=128, BN=256, BK=32; 8 warps (2m x 4n), warp 64x64.
   smem per stage: A 128 rows x 16 words + B 256 rows x 16 words, stride 20 words. */
#define SA_STRIDE 20
#define SB_OFF    2560            /* 128*20 */
#define STAGE_W   7680            /* 2560 + 256*20 */
#define GEMM_SMEM (3*STAGE_W*4)

#define CP16(dst, src) asm volatile("cp.async.cg.shared.global [%0], [%1], 16;" :: "r"(dst), "l"(src))
#define CP_COMMIT()    asm volatile("cp.async.commit_group;" ::: "memory")
#define CP_WAIT1()     asm volatile("cp.async.wait_group 1;" ::: "memory")
#define CP_WAIT0()     asm volatile("cp.async.wait_group 0;" ::: "memory")

__global__ void __launch_bounds__(256) gemm_fp16(int mode, const float* __restrict__ b1,
        const float* __restrict__ W2, const float* __restrict__ b2, float* __restrict__ outc) {
    extern __shared__ uint32_t dsm[];
    const __half* A; const __half* B;
    __half* Ch = 0; const float* bias = 0;
    int K, Nd;
    const int zb = blockIdx.z;
    if (mode == 0) {
        A = g_cseq + (size_t)zb*TB*TP;    B = g_wi16 + (size_t)zb*1536*TP;
        Ch = g_gi + (size_t)zb*TB*1536;   K = 256; Nd = 1536;
    } else if (mode == 1) {
        A = g_h16 + (size_t)zb*BATCH*HID; B = g_wh16 + (size_t)zb*G3*HID;
        Ch = g_gh + (size_t)zb*BATCH*G3;  K = 256; Nd = 768;
    } else {
        A = g_sc16 + (size_t)zb*TB*512;   B = g_w116 + (size_t)zb*HID*512;
        bias = b1 + zb*HID;               K = 512; Nd = 256;
    }
    const int m0 = blockIdx.y * 128;
    const int n0 = blockIdx.x * 256;
    const int tid = threadIdx.x, lane = tid & 31, warp = tid >> 5;
    const int wm = (warp & 1) << 6, wn = (warp >> 1) << 6;
    const int kr = lane & 3, rg = lane >> 2;

    /* loaders: A — 2 threads/row, 32B each; B — 1 thread/row (tid=row), 64B */
    const int lm = tid >> 1, lkh = tid & 1;
    const __half* gA = A + (size_t)(m0 + lm)*K + lkh*16;
    const __half* gB = B + (size_t)(n0 + tid)*K;
    uint32_t smb = (uint32_t)__cvta_generic_to_shared(dsm);
    const uint32_t dA = smb + (uint32_t)(lm*SA_STRIDE + lkh*8)*4;
    const uint32_t dB = smb + (uint32_t)(SB_OFF + tid*SA_STRIDE)*4;

#define ISSUE(kt, s) do {                                     \
    uint32_t so = (uint32_t)(s)*STAGE_W*4;                    \
    const __half* pa = gA + (size_t)(kt)*32;                  \
    CP16(dA + so,      pa);                                   \
    CP16(dA + so + 16, pa + 8);                               \
    const __half* pb = gB + (size_t)(kt)*32;                  \
    CP16(dB + so,      pb);                                   \
    CP16(dB + so + 16, pb + 8);                               \
    CP16(dB + so + 32, pb + 16);                              \
    CP16(dB + so + 48, pb + 24);                              \
} while (0)

    float acc[4][8][4];
    #pragma unroll
    for (int i = 0; i < 4; i++)
        #pragma unroll
        for (int j = 0; j < 8; j++)
            #pragma unroll
            for (int q = 0; q < 4; q++) acc[i][j][q] = 0.f;

    const int nk = K >> 5;
    ISSUE(0, 0); CP_COMMIT();
    ISSUE(1, 1); CP_COMMIT();

    for (int kt = 0; kt < nk; kt++) {
        CP_WAIT1();
        __syncthreads();
        if (kt + 2 < nk) ISSUE(kt + 2, (kt + 2) % 3);
        CP_COMMIT();
        const uint32_t* SAs = dsm + (kt % 3)*STAGE_W;
        const uint32_t* SBs = SAs + SB_OFF;
        #pragma unroll
        for (int cc = 0; cc < 2; cc++) {
            const int kb = cc*8 + kr;
            uint32_t bf[8][2];
            #pragma unroll
            for (int j = 0; j < 8; j++) {
                bf[j][0] = SBs[(wn + 8*j + rg)*SA_STRIDE + kb];
                bf[j][1] = SBs[(wn + 8*j + rg)*SA_STRIDE + kb + 4];
            }
            #pragma unroll
            for (int i = 0; i < 4; i++) {
                const int r = wm + 16*i + rg;
                uint32_t a0 = SAs[ r      *SA_STRIDE + kb];
                uint32_t a1 = SAs[(r + 8) *SA_STRIDE + kb];
                uint32_t a2 = SAs[ r      *SA_STRIDE + kb + 4];
                uint32_t a3 = SAs[(r + 8) *SA_STRIDE + kb + 4];
                #pragma unroll
                for (int j = 0; j < 8; j++) {
                    asm volatile(
                        "mma.sync.aligned.m16n8k16.row.col.f32.f16.f16.f32 "
                        "{%0,%1,%2,%3},{%4,%5,%6,%7},{%8,%9},{%0,%1,%2,%3};"
                        : "+f"(acc[i][j][0]), "+f"(acc[i][j][1]),
                          "+f"(acc[i][j][2]), "+f"(acc[i][j][3])
                        : "r"(a0), "r"(a1), "r"(a2), "r"(a3),
                          "r"(bf[j][0]), "r"(bf[j][1]));
                }
            }
        }
    }
#undef ISSUE

    if (mode < 2) {
        const int cb = kr << 1;
        #pragma unroll
        for (int i = 0; i < 4; i++) {
            #pragma unroll
            for (int j = 0; j < 8; j++) {
                int r0 = m0 + wm + 16*i + rg;
                int c  = n0 + wn + 8*j + cb;
                *(__half2*)(Ch + (size_t)r0*Nd + c)     = __floats2half2_rn(acc[i][j][0], acc[i][j][1]);
                *(__half2*)(Ch + (size_t)(r0+8)*Nd + c) = __floats2half2_rn(acc[i][j][2], acc[i][j][3]);
            }
        }
    } else {
        /* fused: h1 = relu(acc + b1); cm = h1 @ W2^T + b2 */
        const int cb = kr << 1;
        const float* w2a = W2 + (size_t)zb*512;
        const float* w2b = w2a + 256;
        float pr[4][2][2];
        #pragma unroll
        for (int i = 0; i < 4; i++)
            #pragma unroll
            for (int r2 = 0; r2 < 2; r2++) { pr[i][r2][0] = 0.f; pr[i][r2][1] = 0.f; }
        #pragma unroll
        for (int i = 0; i < 4; i++) {
            #pragma unroll
            for (int j = 0; j < 8; j++) {
                int c = wn + 8*j + cb;           /* n0 == 0 */
                float bb0 = bias[c], bb1 = bias[c+1];
                float v0 = fmaxf(acc[i][j][0] + bb0, 0.f);
                float v1 = fmaxf(acc[i][j][1] + bb1, 0.f);
                float v2 = fmaxf(acc[i][j][2] + bb0, 0.f);
                float v3 = fmaxf(acc[i][j][3] + bb1, 0.f);
                float wa0 = __ldg(w2a + c), wa1 = __ldg(w2a + c + 1);
                float wb0 = __ldg(w2b + c), wb1 = __ldg(w2b + c + 1);
                pr[i][0][0] += v0*wa0 + v1*wa1;
                pr[i][0][1] += v0*wb0 + v1*wb1;
                pr[i][1][0] += v2*wa0 + v3*wa1;
                pr[i][1][1] += v2*wb0 + v3*wb1;
            }
        }
        /* reduce over kr quad */
        #pragma unroll
        for (int i = 0; i < 4; i++)
            #pragma unroll
            for (int r2 = 0; r2 < 2; r2++)
                #pragma unroll
                for (int o = 0; o < 2; o++) {
                    float x = pr[i][r2][o];
                    x += __shfl_xor_sync(0xffffffffu, x, 1);
                    x += __shfl_xor_sync(0xffffffffu, x, 2);
                    pr[i][r2][o] = x;
                }
        CP_WAIT0();
        __syncthreads();                          /* all warps done with smem stages */
        float* psm = (float*)dsm;                 /* 128 rows x 2 outputs */
        if (tid < 256) psm[tid] = 0.f;
        __syncthreads();
        if (kr == 0) {
            #pragma unroll
            for (int i = 0; i < 4; i++)
                #pragma unroll
                for (int r2 = 0; r2 < 2; r2++) {
                    int row = wm + 16*i + rg + 8*r2;
                    atomicAdd(&psm[row*2 + 0], pr[i][r2][0]);
                    atomicAdd(&psm[row*2 + 1], pr[i][r2][1]);
                }
        }
        __syncthreads();
        if (tid < 256) {
            int row = tid >> 1, o = tid & 1;
            outc[((size_t)zb*TB + m0 + row)*2 + o] = psm[tid] + b2[zb*2 + o];
        }
    }
}

/* ---------------- GRU gate update (fwd+bwd), step t — 4 elems/thread ---------------- */
__device__ __forceinline__ void h4(const __half* p, float* f) {
    uint2 u = *(const uint2*)p;
    __half2 a = *(__half2*)&u.x, b = *(__half2*)&u.y;
    float2 fa = __half22float2(a), fb = __half22float2(b);
    f[0] = fa.x; f[1] = fa.y; f[2] = fb.x; f[3] = fb.y;
}

__global__ void k_gate(int t) {
    size_t idx = (size_t)blockIdx.x*256 + threadIdx.x;   /* AD*BATCH*64 */
    if (idx >= (size_t)AD*BATCH*64) return;
    int i4 = (int)(idx & 63) * 4;
    int b  = (int)((idx >> 6) & 1023);
    int z  = (int)(idx >> 16);
    int sl = g_seq[b];
    if (t >= sl) return;
    int a = z >> 1, d = z & 1;
    int ot = d ? (sl - 1 - t) : t;
    const __half* gi = g_gi + ((size_t)a*TB + (size_t)ot*BATCH + b)*1536 + d*G3;
    const __half* gh = g_gh + ((size_t)z*BATCH + b)*G3;
    size_t hb = ((size_t)z*BATCH + b)*HID + i4;
    float4 hv = *(const float4*)(g_h + hb);
    float h[4] = {hv.x, hv.y, hv.z, hv.w};
    float gir[4], giz[4], gin[4], ghr[4], ghz[4], ghn[4];
    h4(gi + i4,        gir); h4(gi + HID + i4,   giz); h4(gi + 2*HID + i4, gin);
    h4(gh + i4,        ghr); h4(gh + HID + i4,   ghz); h4(gh + 2*HID + i4, ghn);
    float hn[4];
    #pragma unroll
    for (int q = 0; q < 4; q++) {
        float rr = 1.f/(1.f + expf(-(gir[q] + ghr[q])));
        float zz = 1.f/(1.f + expf(-(giz[q] + ghz[q])));
        float nn = tanhf(gin[q] + rr*ghn[q]);
        hn[q] = (1.f - zz)*nn + zz*h[q];
    }
    *(float4*)(g_h + hb) = make_float4(hn[0], hn[1], hn[2], hn[3]);
    uint2 u; u.x = f2h2(hn[0], hn[1]); u.y = f2h2(hn[2], hn[3]);
    *(uint2*)(g_h16 + hb) = u;
    *(uint2*)(g_out16 + ((size_t)z*TB + (size_t)ot*BATCH + b)*HID + i4) = u;
}

/* ---------------- scatter + LayerNorm (fp16 in, fp16 out) ---------------- */
__global__ void k_scatln(const float* __restrict__ gamma, const float* __restrict__ beta) {
    int j = blockIdx.x, a = blockIdx.y;
    int tid = threadIdx.x;
    int c = tid * 4;
    float v0 = 0.f, v1 = 0.f, v2 = 0.f, v3 = 0.f;
    int msk = (j >= NAG*BATCH) ? 1 : g_mask[j];
    if (msk) {
        int r = g_scatrank[j];
        int d  = (c >= HID) ? 1 : 0;
        int cc = d ? c - HID : c;
        float f[4];
        h4(g_out16 + ((size_t)(a*2 + d)*TB + r)*HID + cc, f);
        v0 = f[0]; v1 = f[1]; v2 = f[2]; v3 = f[3];
    }
    __shared__ float red[128];
    red[tid] = v0 + v1 + v2 + v3;
    __syncthreads();
    for (int st = 64; st > 0; st >>= 1) { if (tid < st) red[tid] += red[tid+st]; __syncthreads(); }
    float mu = red[0] * (1.f/512.f);
    __syncthreads();
    float d0 = v0-mu, d1 = v1-mu, d2 = v2-mu, d3 = v3-mu;
    red[tid] = d0*d0 + d1*d1 + d2*d2 + d3*d3;
    __syncthreads();
    for (int st = 64; st > 0; st >>= 1) { if (tid < st) red[tid] += red[tid+st]; __syncthreads(); }
    float rstd = rsqrtf(red[0]*(1.f/512.f) + 1e-5f);
    float4 gg = ((const float4*)(gamma + (size_t)a*512))[tid];
    float4 bb = ((const float4*)(beta  + (size_t)a*512))[tid];
    float o0 = d0*rstd*gg.x + bb.x;
    float o1 = d1*rstd*gg.y + bb.y;
    float o2 = d2*rstd*gg.z + bb.z;
    float o3 = d3*rstd*gg.w + bb.w;
    uint2 u; u.x = f2h2(o0, o1); u.y = f2h2(o2, o3);
    *(uint2*)(g_sc16 + ((size_t)a*TB + j)*512 + c) = u;
}

__global__ void k_hcopy(float* __restrict__ out) {
    size_t idx = (size_t)blockIdx.x*256 + threadIdx.x;
    if (idx >= (size_t)AD*BATCH*HID/4) return;
    ((float4*)out)[idx] = ((const float4*)g_h)[idx];
}

/* ---------------- launcher ---------------- */
extern "C" void kernel_launch(void* const* d_in, const int* in_sizes, int n_in,
                              void* d_out, int out_size) {
    const float* plans      = (const float*)d_in[0];
    const float* comm_plans = (const float*)d_in[1];
    const float* hx         = (const float*)d_in[2];
    const float* dummy      = (const float*)d_in[3];
    const float* Wi_f       = (const float*)d_in[4];
    const float* Wh_f       = (const float*)d_in[5];
    const float* Wi_b       = (const float*)d_in[6];
    const float* Wh_b       = (const float*)d_in[7];
    const float* ln_g       = (const float*)d_in[8];
    const float* ln_b       = (const float*)d_in[9];
    const float* W1         = (const float*)d_in[10];
    const float* b1         = (const float*)d_in[11];
    const float* W2         = (const float*)d_in[12];
    const float* b2         = (const float*)d_in[13];
    float* out = (float*)d_out;

    cudaFuncSetAttribute(k_scan, cudaFuncAttributeMaxDynamicSharedMemorySize, TB*4);
    cudaFuncSetAttribute(gemm_fp16, cudaFuncAttributeMaxDynamicSharedMemorySize, GEMM_SMEM);

    k_prep<<<BATCH, 256>>>(plans, comm_plans);
    k_scan<<<1, 512, TB*4>>>();
    k_wconv<<<3584, 256>>>(Wi_f, Wi_b, Wh_f, Wh_b, W1);
    k_cseq<<<(NAG*TB*64 + 255)/256, 256>>>(plans, dummy);
    k_hinit<<<(AD*BATCH*HID/4 + 255)/256, 256>>>(hx);

    /* input projections */
    {
        dim3 g(1536/256, TB/128, NAG);
        gemm_fp16<<<g, 256, GEMM_SMEM>>>(0, b1, W2, b2, out);
    }

    /* 16 recurrent steps */
    for (int t = 0; t < NDUM; t++) {
        dim3 g(G3/256, BATCH/128, AD);
        gemm_fp16<<<g, 256, GEMM_SMEM>>>(1, b1, W2, b2, out);
        k_gate<<<(AD*BATCH*64 + 255)/256, 256>>>(t);
    }

    /* final hidden states -> d_out (coord_rnn_hxs region) */
    k_hcopy<<<(AD*BATCH*HID/4 + 255)/256, 256>>>(out + (size_t)NAG*NDUM*BATCH*2);

    /* scatter + LayerNorm -> fp16 scores */
    {
        dim3 g(TB, NAG);
        k_scatln<<<g, 128>>>(ln_g, ln_b);
    }

    /* MLP layer 1 + final projection fused -> coord_masks */
    {
        dim3 g(1, TB/128, NAG);
        gemm_fp16<<<g, 256, GEMM_SMEM>>>(2, b1, W2, b2, out);
    }
}